// round 4
// baseline (speedup 1.0000x reference)
#include <cuda_runtime.h>
#include <math.h>

#define Bsz   32
#define Ssz   20
#define Psz   256
#define HIDN  128
#define MIDN  64
#define G2N   16
#define OBSN  8
#define PREDN 12
#define OUTN  5
#define RROWS (Psz*Bsz)          // 8192 rows, r = p*32 + b  (p-major)
#define ZC    (MIDN+HIDN)        // 192
#define XP_ELEMS (Bsz*PREDN*Psz*3)   // 294912

// ---------------- device scratch ----------------
__device__ float g_c[RROWS*HIDN];          // carry (cell state), 4 MB
__device__ float g_z[RROWS*ZC];            // [e | a], 6 MB
__device__ float g_h[RROWS*HIDN];          // hidden h, 4 MB
__device__ float g_o[RROWS*OUTN];          // last output

__device__ __forceinline__ float sigf(float x){ return 1.f/(1.f+expf(-x)); }

// ---------------- init carry = relu(b_prev) broadcast ----------------
__global__ void k_init(const float* __restrict__ bprev){
  int i = blockIdx.x*256 + threadIdx.x;
  if (i < RROWS*HIDN){ float v = bprev[i & (HIDN-1)]; g_c[i] = v > 0.f ? v : 0.f; }
}

// ---------------- fused mask + hsum-build + soc GEMM + e, writes z = [e|a] ----------------
// Block = (b, 64-p tile), 512 threads. Mask/lists built in-block with warp
// ballots (ascending q within cell == serial-scan order, bit-exact). Then per
// active cell: hsum tile in smem (R0 dual-accumulator even/odd order), GEMM vs
// W_soc slice (cells ascending, k ascending == R0 order).
#define PT     64
#define HS_STR 132
#define WS_STR 132
__global__ void __launch_bounds__(512, 1) k_fused(
    const float* __restrict__ x,
    const float* __restrict__ Wsoc,
    const float* __restrict__ bsoc,
    const float* __restrict__ Win,
    const float* __restrict__ bin,
    int t, int pred){
  extern __shared__ float dyn[];
  float* cs = dyn;                       // 256*128 floats = 128 KB
  float* hs = dyn + Psz*HIDN;            // 64*132
  float* ws = hs + PT*HS_STR;            // 2*16*132
  __shared__ unsigned char ls[PT*Psz];   // 16 KB neighbor lists
  __shared__ int offs[PT*17];
  __shared__ int gl[G2N];
  __shared__ int s_ng;
  __shared__ unsigned int s_un;
  __shared__ float qpid[Psz], qpx[Psz], qpy[Psz];

  int b = blockIdx.x, pbase = blockIdx.y*PT;
  int tid = threadIdx.x;
  float4* cs4 = (float4*)cs;

  // load c[:,b,:] (all 256 p rows for this b)
  for (int i = tid; i < Psz*HIDN/4; i += 512){
    int o = i>>5, q = i&31;
    cs4[i] = *(const float4*)(g_c + ((size_t)o*Bsz + b)*HIDN + q*4);
  }
  // batch-0 positions / pids for the mask
  if (tid < Psz){
    int q = tid;
    if (pred){
      qpid[q] = x[((size_t)(Ssz-1)*Psz + q)*3 + 0];
      qpx[q]  = g_o[(q*Bsz + 0)*OUTN + 0];
      qpy[q]  = g_o[(q*Bsz + 0)*OUTN + 1];
    } else {
      const float* xb = x + (size_t)(t*Psz)*3;
      qpid[q] = xb[q*3+0]; qpx[q] = xb[q*3+1]; qpy[q] = xb[q*3+2];
    }
  }
  if (tid == 0) s_un = 0u;
  __syncthreads();

  int tx = tid & 31, ty = tid >> 5;     // 16 warps

  // ---- mask + ordered neighbor lists (warp ty owns rows ty*4..ty*4+3) ----
  {
    const float CELLF = 0.1f;
    unsigned int lt = (1u << tx) - 1u;
    for (int pi = 0; pi < 4; pi++){
      int pl = ty*4 + pi, p = pbase + pl;
      float pxv = qpx[p], pyv = qpy[p], pidv = qpid[p];
      float lx = pxv-0.2f, rxb = pxv+0.2f, by = pyv-0.2f, tyv = pyv+0.2f;
      unsigned char gr[8];
      #pragma unroll
      for (int c = 0; c < 8; c++){
        int q = c*32 + tx;
        float ox = qpx[q], oy = qpy[q];
        bool inb   = (ox < rxb) && (ox >= lx) && (oy < tyv) && (oy >= by);
        bool valid = (pidv != 0.f) && (qpid[q] != 0.f) && (pidv != qpid[q]);
        int cx = (int)floorf((ox - lx)/CELLF);
        int cy = (int)floorf((oy - by)/CELLF);
        int idx = cx + cy*4; idx = idx < 0 ? 0 : (idx > 15 ? 15 : idx);
        gr[c] = (inb && valid) ? (unsigned char)idx : (unsigned char)255;
      }
      int base = 0; unsigned int act = 0;
      #pragma unroll
      for (int g = 0; g < 16; g++){
        if (tx == 0) offs[pl*17 + g] = base;
        int cum = 0;
        #pragma unroll
        for (int c = 0; c < 8; c++){
          unsigned int m = __ballot_sync(0xffffffffu, gr[c] == (unsigned char)g);
          if (gr[c] == (unsigned char)g)
            ls[pl*Psz + base + cum + __popc(m & lt)] = (unsigned char)(c*32 + tx);
          cum += __popc(m);
        }
        if (cum) act |= (1u << g);
        base += cum;
      }
      if (tx == 0){
        offs[pl*17 + 16] = base;
        if (act) atomicOr(&s_un, act);
      }
    }
  }
  __syncthreads();
  if (tid == 0){
    unsigned int u = s_un; int n = 0;
    for (int g = 0; g < 16; g++) if ((u>>g)&1u) gl[n++] = g;
    s_ng = n;
  }
  __syncthreads();
  int ng = s_ng;

  // GEMM thread mapping: warp-group wg covers 64 n-cols, rows by (ty&7)
  int wg = ty >> 3;
  int m0 = (ty & 7)*8;
  int n0 = wg*64 + tx*2;
  float acc[8][2];
  #pragma unroll
  for (int i = 0; i < 8; i++){ acc[i][0] = 0.f; acc[i][1] = 0.f; }

  if (ng > 0){
    int wn0 = tid >> 2, wk0 = (tid & 3)*4;   // 512 threads: one float4 each
    float4 pv0 = *(const float4*)(Wsoc + (size_t)wn0*2048 + gl[0]*128 + wk0);
    int buf = 0;
    for (int gi = 0; gi < ng; gi++){
      int g = gl[gi];
      // ---- hsum tile [64 p][128 f]: EXACT dual-accumulator even/odd order ----
      #pragma unroll
      for (int i2 = 0; i2 < 4; i2++){
        int pl = ty*4 + i2;
        int s = offs[pl*17 + g], e = offs[pl*17 + g + 1];
        float4 a0 = make_float4(0.f,0.f,0.f,0.f);
        float4 a1 = make_float4(0.f,0.f,0.f,0.f);
        int j = s;
        for (; j+1 < e; j += 2){
          float4 v0 = cs4[(int)ls[pl*Psz + j]*32 + tx];
          float4 v1 = cs4[(int)ls[pl*Psz + j+1]*32 + tx];
          a0.x += v0.x; a0.y += v0.y; a0.z += v0.z; a0.w += v0.w;
          a1.x += v1.x; a1.y += v1.y; a1.z += v1.z; a1.w += v1.w;
        }
        if (j < e){
          float4 v0 = cs4[(int)ls[pl*Psz + j]*32 + tx];
          a0.x += v0.x; a0.y += v0.y; a0.z += v0.z; a0.w += v0.w;
        }
        float4 r;
        r.x = a0.x + a1.x; r.y = a0.y + a1.y;
        r.z = a0.z + a1.z; r.w = a0.w + a1.w;
        *(float4*)(hs + pl*HS_STR + tx*4) = r;
      }
      __syncthreads();                      // hs ready
      // ---- GEMM over this g's K=128, kc chunks of 16, ping-pong W tiles ----
      for (int kc = 0; kc < 8; kc++){
        float* wb = ws + buf*16*WS_STR;
        wb[(wk0+0)*WS_STR + wn0] = pv0.x;
        wb[(wk0+1)*WS_STR + wn0] = pv0.y;
        wb[(wk0+2)*WS_STR + wn0] = pv0.z;
        wb[(wk0+3)*WS_STR + wn0] = pv0.w;
        __syncthreads();                    // wb visible
        int nkc = kc + 1, ngi = gi;
        if (nkc == 8){ nkc = 0; ngi = gi + 1; }
        if (ngi < ng)
          pv0 = *(const float4*)(Wsoc + (size_t)wn0*2048 + gl[ngi]*128 + nkc*16 + wk0);
        #pragma unroll
        for (int kq = 0; kq < 4; kq++){
          float4 hv[8];
          #pragma unroll
          for (int i = 0; i < 8; i++)
            hv[i] = *(const float4*)(hs + (m0+i)*HS_STR + kc*16 + kq*4);
          #pragma unroll
          for (int kk = 0; kk < 4; kk++){
            float2 w = *(const float2*)(wb + (kq*4+kk)*WS_STR + n0);
            #pragma unroll
            for (int i = 0; i < 8; i++){
              float h = ((const float*)&hv[i])[kk];
              acc[i][0] += h*w.x; acc[i][1] += h*w.y;
            }
          }
        }
        buf ^= 1;
      }
      __syncthreads();                      // protect hs before next build
    }
  }

  // ---- epilogue: a = relu(acc + b_soc) -> z[:,64:192] ----
  float2 bv = *(const float2*)(bsoc + n0);
  #pragma unroll
  for (int i = 0; i < 8; i++){
    int r = (pbase + m0 + i)*Bsz + b;
    float2 o;
    o.x = fmaxf(acc[i][0] + bv.x, 0.f);
    o.y = fmaxf(acc[i][1] + bv.y, 0.f);
    *(float2*)(g_z + (size_t)r*ZC + MIDN + n0) = o;
  }
  // ---- e = relu(pos @ Win^T + bin) -> z[:,0:64] ----
  for (int i2 = tid; i2 < PT*MIDN; i2 += 512){
    int mm = i2 >> 6, j = i2 & 63;
    int p = pbase + mm;
    int r = p*Bsz + b;
    float px, py;
    if (pred){ px = g_o[r*OUTN+0]; py = g_o[r*OUTN+1]; }
    else {
      const float* xr = x + (size_t)(((b*Ssz)+t)*Psz + p)*3;
      px = xr[1]; py = xr[2];
    }
    float v = px*Win[j*2+0] + py*Win[j*2+1] + bin[j];
    g_z[(size_t)r*ZC + j] = v > 0.f ? v : 0.f;
  }
}

// ---------------- LSTM gates (i,g,o only; f is dead) -> c, h ----------------
__global__ void k_lstm(const float* __restrict__ Wih,
                       const float* __restrict__ bih,
                       const float* __restrict__ bhh){
  __shared__ float Zs[16][68];
  __shared__ float Wg3[3][16][36];
  int mt = blockIdx.x, jt = blockIdx.y;
  int r0 = mt*64, j0 = jt*32;
  int tI = threadIdx.x;
  int tx = tI & 31, ty = tI >> 5;
  int m0 = ty*8;
  float ai[8], ag[8], ao[8];
  #pragma unroll
  for (int i = 0; i < 8; i++){ ai[i]=0.f; ag[i]=0.f; ao[i]=0.f; }
  int lm = tI >> 2, lk = (tI & 3)*4;
  for (int kc = 0; kc < 12; kc++){
    int kb = kc*16;
    float4 zv = *(const float4*)(g_z + (size_t)(r0+lm)*ZC + kb + lk);
    float4 wv[2]; int wg[2], wj[2], wk[2]; bool wval[2];
    #pragma unroll
    for (int i = 0; i < 2; i++){
      int idx = tI + i*256; wval[i] = idx < 384;
      wg[i]=0; wj[i]=0; wk[i]=0;
      if (wval[i]){
        wg[i] = idx/128; int rs = idx%128; wj[i] = rs>>2; wk[i] = (rs&3)*4;
        int baser = (wg[i]==0?0:(wg[i]==1?256:384)) + j0 + wj[i];
        wv[i] = *(const float4*)(Wih + (size_t)baser*ZC + kb + wk[i]);
      }
    }
    __syncthreads();
    Zs[lk+0][lm]=zv.x; Zs[lk+1][lm]=zv.y; Zs[lk+2][lm]=zv.z; Zs[lk+3][lm]=zv.w;
    #pragma unroll
    for (int i = 0; i < 2; i++){
      if (wval[i]){
        Wg3[wg[i]][wk[i]+0][wj[i]]=wv[i].x; Wg3[wg[i]][wk[i]+1][wj[i]]=wv[i].y;
        Wg3[wg[i]][wk[i]+2][wj[i]]=wv[i].z; Wg3[wg[i]][wk[i]+3][wj[i]]=wv[i].w;
      }
    }
    __syncthreads();
    #pragma unroll
    for (int kk = 0; kk < 16; kk++){
      float4 z0 = *(const float4*)(&Zs[kk][m0]);
      float4 z1 = *(const float4*)(&Zs[kk][m0+4]);
      float zz[8] = {z0.x,z0.y,z0.z,z0.w,z1.x,z1.y,z1.z,z1.w};
      float wi = Wg3[0][kk][tx], wgg = Wg3[1][kk][tx], wo = Wg3[2][kk][tx];
      #pragma unroll
      for (int i = 0; i < 8; i++){
        ai[i] += zz[i]*wi; ag[i] += zz[i]*wgg; ao[i] += zz[i]*wo;
      }
    }
    __syncthreads();
  }
  int j = j0 + tx;
  float bi_ = bih[j]       + bhh[j];
  float bg_ = bih[256 + j] + bhh[256 + j];
  float bo_ = bih[384 + j] + bhh[384 + j];
  #pragma unroll
  for (int i = 0; i < 8; i++){
    int r = r0 + m0 + i;
    float ci = sigf(ai[i]+bi_)*tanhf(ag[i]+bg_);
    float hh = sigf(ao[i]+bo_)*tanhf(ci);
    g_c[(size_t)r*HIDN + j] = ci;
    g_h[(size_t)r*HIDN + j] = hh;
  }
}

// ---------------- output head o = h @ Wout^T + bout (+ op write, + xp write) ----------------
__global__ void k_out(const float* __restrict__ Wout, const float* __restrict__ bout,
                      const float* __restrict__ x, float* __restrict__ out,
                      int wr_op, int kstep, int wr_xp, int xpk){
  int warp = threadIdx.x >> 5, lane = threadIdx.x & 31;
  int r = blockIdx.x*8 + warp;
  float hv[4];
  #pragma unroll
  for (int i = 0; i < 4; i++) hv[i] = g_h[(size_t)r*HIDN + lane + i*32];
  float res[5];
  #pragma unroll
  for (int c = 0; c < 5; c++){
    float s = 0.f;
    #pragma unroll
    for (int i = 0; i < 4; i++) s += hv[i]*__ldg(Wout + c*HIDN + lane + i*32);
    #pragma unroll
    for (int d = 16; d > 0; d >>= 1) s += __shfl_xor_sync(0xffffffffu, s, d);
    res[c] = s + bout[c];
  }
  if (lane == 0){
    int b = r & 31, p = r >> 5;
    #pragma unroll
    for (int c = 0; c < 5; c++){
      g_o[r*OUTN + c] = res[c];
      if (wr_op)
        out[(size_t)XP_ELEMS + ((size_t)(b*PREDN + kstep)*Psz + p)*OUTN + c] = res[c];
    }
    if (wr_xp){
      float pid = x[((size_t)(b*Ssz + Ssz-1)*Psz + p)*3 + 0];
      size_t base = ((size_t)(b*PREDN + xpk)*Psz + p)*3;
      out[base+0] = pid;
      out[base+1] = res[0];
      out[base+2] = res[1];
    }
  }
}

// ---------------- launch ----------------
extern "C" void kernel_launch(void* const* d_in, const int* in_sizes, int n_in,
                              void* d_out, int out_size){
  const float* x    = (const float*)d_in[0];
  const float* Win  = (const float*)d_in[1];
  const float* bin  = (const float*)d_in[2];
  const float* Wsoc = (const float*)d_in[3];
  const float* bsoc = (const float*)d_in[4];
  const float* bprev= (const float*)d_in[5];
  const float* Wih  = (const float*)d_in[6];
  const float* bih  = (const float*)d_in[7];
  const float* bhh  = (const float*)d_in[8];
  const float* Wout = (const float*)d_in[9];
  const float* bout = (const float*)d_in[10];
  float* out = (float*)d_out;

  const int DYN = (Psz*HIDN + PT*HS_STR + 2*16*WS_STR)*(int)sizeof(float);
  cudaFuncSetAttribute(k_fused, cudaFuncAttributeMaxDynamicSharedMemorySize, DYN);

  k_init<<<(RROWS*HIDN + 255)/256, 256>>>(bprev);
  for (int t = 0; t < OBSN; t++){
    k_fused<<<dim3(Bsz, Psz/PT), 512, DYN>>>(x, Wsoc, bsoc, Win, bin, t, 0);
    k_lstm<<<dim3(RROWS/64, 4), 256>>>(Wih, bih, bhh);
    if (t == OBSN-1)
      k_out<<<RROWS/8, 256>>>(Wout, bout, x, out, 0, 0, 1, 0);   // g_o + xp[0]
  }
  for (int k = 0; k < PREDN; k++){
    k_fused<<<dim3(Bsz, Psz/PT), 512, DYN>>>(x, Wsoc, bsoc, Win, bin, 0, 1);
    k_lstm<<<dim3(RROWS/64, 4), 256>>>(Wih, bih, bhh);
    k_out<<<RROWS/8, 256>>>(Wout, bout, x, out, 1, k, (k < PREDN-1) ? 1 : 0, k+1);
  }
}

// round 6
// speedup vs baseline: 1.0318x; 1.0318x over previous
#include <cuda_runtime.h>
#include <math.h>

#define Bsz   32
#define Ssz   20
#define Psz   256
#define HIDN  128
#define MIDN  64
#define G2N   16
#define OBSN  8
#define PREDN 12
#define OUTN  5
#define RROWS (Psz*Bsz)          // 8192 rows, r = p*32 + b  (p-major)
#define ZC    (MIDN+HIDN)        // 192
#define XP_ELEMS (Bsz*PREDN*Psz*3)   // 294912

// ---------------- device scratch ----------------
__device__ float g_c[RROWS*HIDN];          // carry (cell state), 4 MB
__device__ float g_z[RROWS*ZC];            // [e | a], 6 MB
__device__ float g_h[RROWS*HIDN];          // hidden h, 4 MB
__device__ float g_o[RROWS*OUTN];          // last output

__device__ __forceinline__ float sigf(float x){ return 1.f/(1.f+expf(-x)); }

// ---------------- init carry = relu(b_prev) broadcast ----------------
__global__ void k_init(const float* __restrict__ bprev){
  int i = blockIdx.x*256 + threadIdx.x;
  if (i < RROWS*HIDN){ float v = bprev[i & (HIDN-1)]; g_c[i] = v > 0.f ? v : 0.f; }
}

// ---------------- fused mask + hsum-build + soc GEMM + e, writes z = [e|a] ----------------
// Block = (b, 64-p tile), 256 threads (R3-proven GEMM mapping: 8 warps, 8x4/thread).
// Mask/lists built in-block with warp ballots (ascending q within cell == serial
// scan order, bit-exact). Per active cell: hsum tile in smem (dual-accumulator
// even/odd order), GEMM vs W_soc slice (cells ascending, k ascending).
#define PT     64
#define HS_STR 132
#define WS_STR 132
__global__ void __launch_bounds__(256, 1) k_fused(
    const float* __restrict__ x,
    const float* __restrict__ Wsoc,
    const float* __restrict__ bsoc,
    const float* __restrict__ Win,
    const float* __restrict__ bin,
    int t, int pred){
  extern __shared__ float dyn[];
  float* cs = dyn;                       // 256*128 floats = 128 KB
  float* hs = dyn + Psz*HIDN;            // 64*132
  float* ws = hs + PT*HS_STR;            // 2*16*132
  __shared__ unsigned char ls[PT*Psz];   // 16 KB neighbor lists
  __shared__ int offs[PT*17];
  __shared__ int gl[G2N];
  __shared__ int s_ng;
  __shared__ unsigned int s_un;
  __shared__ float qpid[Psz], qpx[Psz], qpy[Psz];

  int b = blockIdx.x, pbase = blockIdx.y*PT;
  int tid = threadIdx.x;
  float4* cs4 = (float4*)cs;

  // load c[:,b,:] (all 256 p rows for this b)
  for (int i = tid; i < Psz*HIDN/4; i += 256){
    int o = i>>5, q = i&31;
    cs4[i] = *(const float4*)(g_c + ((size_t)o*Bsz + b)*HIDN + q*4);
  }
  // batch-0 positions / pids for the mask (256 threads == 256 q's)
  {
    int q = tid;
    if (pred){
      qpid[q] = x[((size_t)(Ssz-1)*Psz + q)*3 + 0];
      qpx[q]  = g_o[(q*Bsz + 0)*OUTN + 0];
      qpy[q]  = g_o[(q*Bsz + 0)*OUTN + 1];
    } else {
      const float* xb = x + (size_t)(t*Psz)*3;
      qpid[q] = xb[q*3+0]; qpx[q] = xb[q*3+1]; qpy[q] = xb[q*3+2];
    }
  }
  if (tid == 0) s_un = 0u;
  __syncthreads();

  int tx = tid & 31, ty = tid >> 5;     // 8 warps

  // ---- mask + ordered neighbor lists (warp ty owns rows ty*8..ty*8+7) ----
  {
    const float CELLF = 0.1f;
    unsigned int lt = (1u << tx) - 1u;
    for (int pi = 0; pi < 8; pi++){
      int pl = ty*8 + pi, p = pbase + pl;
      float pxv = qpx[p], pyv = qpy[p], pidv = qpid[p];
      float lx = pxv-0.2f, rxb = pxv+0.2f, by = pyv-0.2f, tyv = pyv+0.2f;
      unsigned char gr[8];
      #pragma unroll
      for (int c = 0; c < 8; c++){
        int q = c*32 + tx;
        float ox = qpx[q], oy = qpy[q];
        bool inb   = (ox < rxb) && (ox >= lx) && (oy < tyv) && (oy >= by);
        bool valid = (pidv != 0.f) && (qpid[q] != 0.f) && (pidv != qpid[q]);
        int cx = (int)floorf((ox - lx)/CELLF);
        int cy = (int)floorf((oy - by)/CELLF);
        int idx = cx + cy*4; idx = idx < 0 ? 0 : (idx > 15 ? 15 : idx);
        gr[c] = (inb && valid) ? (unsigned char)idx : (unsigned char)255;
      }
      int base = 0; unsigned int act = 0;
      #pragma unroll
      for (int g = 0; g < 16; g++){
        if (tx == 0) offs[pl*17 + g] = base;
        int cum = 0;
        #pragma unroll
        for (int c = 0; c < 8; c++){
          unsigned int m = __ballot_sync(0xffffffffu, gr[c] == (unsigned char)g);
          if (gr[c] == (unsigned char)g)
            ls[pl*Psz + base + cum + __popc(m & lt)] = (unsigned char)(c*32 + tx);
          cum += __popc(m);
        }
        if (cum) act |= (1u << g);
        base += cum;
      }
      if (tx == 0){
        offs[pl*17 + 16] = base;
        if (act) atomicOr(&s_un, act);
      }
    }
  }
  __syncthreads();
  if (tid == 0){
    unsigned int u = s_un; int n = 0;
    for (int g = 0; g < 16; g++) if ((u>>g)&1u) gl[n++] = g;
    s_ng = n;
  }
  __syncthreads();
  int ng = s_ng;

  // GEMM thread mapping (R3): n0 = tx*4 (128 cols), m0 = ty*8 (64 rows)
  int n0 = tx*4, m0 = ty*8;
  float acc[8][4];
  #pragma unroll
  for (int i = 0; i < 8; i++){
    #pragma unroll
    for (int j = 0; j < 4; j++) acc[i][j] = 0.f;
  }

  if (ng > 0){
    // W tile loader: each thread owns 2 float4 (n-row, k-quad)
    int idx0 = tid, idx1 = tid + 256;
    int wn0 = idx0 >> 2, wk0 = (idx0 & 3)*4;
    int wn1 = idx1 >> 2, wk1 = (idx1 & 3)*4;
    float4 pv0, pv1;
    {
      int g = gl[0];
      pv0 = *(const float4*)(Wsoc + (size_t)wn0*2048 + g*128 + wk0);
      pv1 = *(const float4*)(Wsoc + (size_t)wn1*2048 + g*128 + wk1);
    }
    int buf = 0;
    for (int gi = 0; gi < ng; gi++){
      int g = gl[gi];
      // ---- hsum tile [64 p][128 f]: EXACT dual-accumulator even/odd order ----
      #pragma unroll
      for (int i2 = 0; i2 < 8; i2++){
        int pl = ty*8 + i2;
        int s = offs[pl*17 + g], e = offs[pl*17 + g + 1];
        float4 a0 = make_float4(0.f,0.f,0.f,0.f);
        float4 a1 = make_float4(0.f,0.f,0.f,0.f);
        int j = s;
        for (; j+1 < e; j += 2){
          float4 v0 = cs4[(int)ls[pl*Psz + j]*32 + tx];
          float4 v1 = cs4[(int)ls[pl*Psz + j+1]*32 + tx];
          a0.x += v0.x; a0.y += v0.y; a0.z += v0.z; a0.w += v0.w;
          a1.x += v1.x; a1.y += v1.y; a1.z += v1.z; a1.w += v1.w;
        }
        if (j < e){
          float4 v0 = cs4[(int)ls[pl*Psz + j]*32 + tx];
          a0.x += v0.x; a0.y += v0.y; a0.z += v0.z; a0.w += v0.w;
        }
        float4 r;
        r.x = a0.x + a1.x; r.y = a0.y + a1.y;
        r.z = a0.z + a1.z; r.w = a0.w + a1.w;
        *(float4*)(hs + pl*HS_STR + tx*4) = r;
      }
      __syncthreads();                      // hs ready
      // ---- GEMM over this g's K=128, kc chunks of 16, ping-pong W tiles ----
      for (int kc = 0; kc < 8; kc++){
        float* wb = ws + buf*16*WS_STR;
        wb[(wk0+0)*WS_STR + wn0] = pv0.x;
        wb[(wk0+1)*WS_STR + wn0] = pv0.y;
        wb[(wk0+2)*WS_STR + wn0] = pv0.z;
        wb[(wk0+3)*WS_STR + wn0] = pv0.w;
        wb[(wk1+0)*WS_STR + wn1] = pv1.x;
        wb[(wk1+1)*WS_STR + wn1] = pv1.y;
        wb[(wk1+2)*WS_STR + wn1] = pv1.z;
        wb[(wk1+3)*WS_STR + wn1] = pv1.w;
        __syncthreads();                    // wb visible
        int nkc = kc + 1, ngi = gi;
        if (nkc == 8){ nkc = 0; ngi = gi + 1; }
        if (ngi < ng){
          int gg = gl[ngi];
          pv0 = *(const float4*)(Wsoc + (size_t)wn0*2048 + gg*128 + nkc*16 + wk0);
          pv1 = *(const float4*)(Wsoc + (size_t)wn1*2048 + gg*128 + nkc*16 + wk1);
        }
        #pragma unroll
        for (int kq = 0; kq < 4; kq++){
          float4 hv[8];
          #pragma unroll
          for (int i = 0; i < 8; i++)
            hv[i] = *(const float4*)(hs + (m0+i)*HS_STR + kc*16 + kq*4);
          #pragma unroll
          for (int kk = 0; kk < 4; kk++){
            float4 w = *(const float4*)(wb + (kq*4+kk)*WS_STR + n0);
            #pragma unroll
            for (int i = 0; i < 8; i++){
              float h = ((const float*)&hv[i])[kk];
              acc[i][0] += h*w.x; acc[i][1] += h*w.y;
              acc[i][2] += h*w.z; acc[i][3] += h*w.w;
            }
          }
        }
        buf ^= 1;
      }
      __syncthreads();                      // protect hs before next build
    }
  }

  // ---- epilogue: a = relu(acc + b_soc) -> z[:,64:192] ----
  float4 bv = *(const float4*)(bsoc + n0);
  #pragma unroll
  for (int i = 0; i < 8; i++){
    int r = (pbase + m0 + i)*Bsz + b;
    float4 o;
    o.x = fmaxf(acc[i][0] + bv.x, 0.f);
    o.y = fmaxf(acc[i][1] + bv.y, 0.f);
    o.z = fmaxf(acc[i][2] + bv.z, 0.f);
    o.w = fmaxf(acc[i][3] + bv.w, 0.f);
    *(float4*)(g_z + (size_t)r*ZC + MIDN + n0) = o;
  }
  // ---- e = relu(pos @ Win^T + bin) -> z[:,0:64] ----
  for (int i2 = tid; i2 < PT*MIDN; i2 += 256){
    int mm = i2 >> 6, j = i2 & 63;
    int p = pbase + mm;
    int r = p*Bsz + b;
    float px, py;
    if (pred){ px = g_o[r*OUTN+0]; py = g_o[r*OUTN+1]; }
    else {
      const float* xr = x + (size_t)(((b*Ssz)+t)*Psz + p)*3;
      px = xr[1]; py = xr[2];
    }
    float v = px*Win[j*2+0] + py*Win[j*2+1] + bin[j];
    g_z[(size_t)r*ZC + j] = v > 0.f ? v : 0.f;
  }
}

// ---------------- LSTM gates (i,g,o only; f is dead) -> c, h ----------------
__global__ void k_lstm(const float* __restrict__ Wih,
                       const float* __restrict__ bih,
                       const float* __restrict__ bhh){
  __shared__ float Zs[16][68];
  __shared__ float Wg3[3][16][36];
  int mt = blockIdx.x, jt = blockIdx.y;
  int r0 = mt*64, j0 = jt*32;
  int tI = threadIdx.x;
  int tx = tI & 31, ty = tI >> 5;
  int m0 = ty*8;
  float ai[8], ag[8], ao[8];
  #pragma unroll
  for (int i = 0; i < 8; i++){ ai[i]=0.f; ag[i]=0.f; ao[i]=0.f; }
  int lm = tI >> 2, lk = (tI & 3)*4;
  for (int kc = 0; kc < 12; kc++){
    int kb = kc*16;
    float4 zv = *(const float4*)(g_z + (size_t)(r0+lm)*ZC + kb + lk);
    float4 wv[2]; int wg[2], wj[2], wk[2]; bool wval[2];
    #pragma unroll
    for (int i = 0; i < 2; i++){
      int idx = tI + i*256; wval[i] = idx < 384;
      wg[i]=0; wj[i]=0; wk[i]=0;
      if (wval[i]){
        wg[i] = idx/128; int rs = idx%128; wj[i] = rs>>2; wk[i] = (rs&3)*4;
        int baser = (wg[i]==0?0:(wg[i]==1?256:384)) + j0 + wj[i];
        wv[i] = *(const float4*)(Wih + (size_t)baser*ZC + kb + wk[i]);
      }
    }
    __syncthreads();
    Zs[lk+0][lm]=zv.x; Zs[lk+1][lm]=zv.y; Zs[lk+2][lm]=zv.z; Zs[lk+3][lm]=zv.w;
    #pragma unroll
    for (int i = 0; i < 2; i++){
      if (wval[i]){
        Wg3[wg[i]][wk[i]+0][wj[i]]=wv[i].x; Wg3[wg[i]][wk[i]+1][wj[i]]=wv[i].y;
        Wg3[wg[i]][wk[i]+2][wj[i]]=wv[i].z; Wg3[wg[i]][wk[i]+3][wj[i]]=wv[i].w;
      }
    }
    __syncthreads();
    #pragma unroll
    for (int kk = 0; kk < 16; kk++){
      float4 z0 = *(const float4*)(&Zs[kk][m0]);
      float4 z1 = *(const float4*)(&Zs[kk][m0+4]);
      float zz[8] = {z0.x,z0.y,z0.z,z0.w,z1.x,z1.y,z1.z,z1.w};
      float wi = Wg3[0][kk][tx], wgg = Wg3[1][kk][tx], wo = Wg3[2][kk][tx];
      #pragma unroll
      for (int i = 0; i < 8; i++){
        ai[i] += zz[i]*wi; ag[i] += zz[i]*wgg; ao[i] += zz[i]*wo;
      }
    }
    __syncthreads();
  }
  int j = j0 + tx;
  float bi_ = bih[j]       + bhh[j];
  float bg_ = bih[256 + j] + bhh[256 + j];
  float bo_ = bih[384 + j] + bhh[384 + j];
  #pragma unroll
  for (int i = 0; i < 8; i++){
    int r = r0 + m0 + i;
    float ci = sigf(ai[i]+bi_)*tanhf(ag[i]+bg_);
    float hh = sigf(ao[i]+bo_)*tanhf(ci);
    g_c[(size_t)r*HIDN + j] = ci;
    g_h[(size_t)r*HIDN + j] = hh;
  }
}

// ---------------- output head o = h @ Wout^T + bout (+ op write, + xp write) ----------------
__global__ void k_out(const float* __restrict__ Wout, const float* __restrict__ bout,
                      const float* __restrict__ x, float* __restrict__ out,
                      int wr_op, int kstep, int wr_xp, int xpk){
  int warp = threadIdx.x >> 5, lane = threadIdx.x & 31;
  int r = blockIdx.x*8 + warp;
  float hv[4];
  #pragma unroll
  for (int i = 0; i < 4; i++) hv[i] = g_h[(size_t)r*HIDN + lane + i*32];
  float res[5];
  #pragma unroll
  for (int c = 0; c < 5; c++){
    float s = 0.f;
    #pragma unroll
    for (int i = 0; i < 4; i++) s += hv[i]*__ldg(Wout + c*HIDN + lane + i*32);
    #pragma unroll
    for (int d = 16; d > 0; d >>= 1) s += __shfl_xor_sync(0xffffffffu, s, d);
    res[c] = s + bout[c];
  }
  if (lane == 0){
    int b = r & 31, p = r >> 5;
    #pragma unroll
    for (int c = 0; c < 5; c++){
      g_o[r*OUTN + c] = res[c];
      if (wr_op)
        out[(size_t)XP_ELEMS + ((size_t)(b*PREDN + kstep)*Psz + p)*OUTN + c] = res[c];
    }
    if (wr_xp){
      float pid = x[((size_t)(b*Ssz + Ssz-1)*Psz + p)*3 + 0];
      size_t base = ((size_t)(b*PREDN + xpk)*Psz + p)*3;
      out[base+0] = pid;
      out[base+1] = res[0];
      out[base+2] = res[1];
    }
  }
}

// ---------------- launch ----------------
extern "C" void kernel_launch(void* const* d_in, const int* in_sizes, int n_in,
                              void* d_out, int out_size){
  const float* x    = (const float*)d_in[0];
  const float* Win  = (const float*)d_in[1];
  const float* bin  = (const float*)d_in[2];
  const float* Wsoc = (const float*)d_in[3];
  const float* bsoc = (const float*)d_in[4];
  const float* bprev= (const float*)d_in[5];
  const float* Wih  = (const float*)d_in[6];
  const float* bih  = (const float*)d_in[7];
  const float* bhh  = (const float*)d_in[8];
  const float* Wout = (const float*)d_in[9];
  const float* bout = (const float*)d_in[10];
  float* out = (float*)d_out;

  const int DYN = (Psz*HIDN + PT*HS_STR + 2*16*WS_STR)*(int)sizeof(float);
  cudaFuncSetAttribute(k_fused, cudaFuncAttributeMaxDynamicSharedMemorySize, DYN);

  k_init<<<(RROWS*HIDN + 255)/256, 256>>>(bprev);
  for (int t = 0; t < OBSN; t++){
    k_fused<<<dim3(Bsz, Psz/PT), 256, DYN>>>(x, Wsoc, bsoc, Win, bin, t, 0);
    k_lstm<<<dim3(RROWS/64, 4), 256>>>(Wih, bih, bhh);
    if (t == OBSN-1)
      k_out<<<RROWS/8, 256>>>(Wout, bout, x, out, 0, 0, 1, 0);   // g_o + xp[0]
  }
  for (int k = 0; k < PREDN; k++){
    k_fused<<<dim3(Bsz, Psz/PT), 256, DYN>>>(x, Wsoc, bsoc, Win, bin, 0, 1);
    k_lstm<<<dim3(RROWS/64, 4), 256>>>(Wih, bih, bhh);
    k_out<<<RROWS/8, 256>>>(Wout, bout, x, out, 1, k, (k < PREDN-1) ? 1 : 0, k+1);
  }
}

// round 7
// speedup vs baseline: 1.1211x; 1.0866x over previous
#include <cuda_runtime.h>
#include <math.h>

#define Bsz   32
#define Ssz   20
#define Psz   256
#define HIDN  128
#define MIDN  64
#define G2N   16
#define OBSN  8
#define PREDN 12
#define OUTN  5
#define RROWS (Psz*Bsz)          // 8192 rows, r = p*32 + b  (p-major)
#define ZC    (MIDN+HIDN)        // 192
#define XP_ELEMS (Bsz*PREDN*Psz*3)   // 294912

// ---------------- device scratch ----------------
__device__ float g_c[RROWS*HIDN];          // carry (cell state), 4 MB
__device__ float g_z[RROWS*ZC];            // [e | a], 6 MB
__device__ float g_h[RROWS*HIDN];          // hidden h, 4 MB
__device__ float g_o[RROWS*OUTN];          // last output
__device__ float g_Wt[2048*HIDN];          // W_soc transposed [k][n], 1 MB
__device__ unsigned char g_list[Psz*Psz];  // per-p neighbor ids grouped by cell
__device__ int g_off[Psz*(G2N+1)];         // per-p per-cell offsets
__device__ unsigned int g_active[Psz];     // per-p active-cell bitmask

__device__ __forceinline__ float sigf(float x){ return 1.f/(1.f+expf(-x)); }

// ---------------- init carry = relu(b_prev) broadcast ----------------
__global__ void k_init(const float* __restrict__ bprev){
  int i = blockIdx.x*256 + threadIdx.x;
  if (i < RROWS*HIDN){ float v = bprev[i & (HIDN-1)]; g_c[i] = v > 0.f ? v : 0.f; }
}

// ---------------- one-time transpose of W_soc [128][2048] -> g_Wt [2048][128] ----------------
__global__ void k_wt(const float* __restrict__ Wsoc){
  int i = blockIdx.x*256 + threadIdx.x;     // i over 128*2048
  if (i < HIDN*2048){
    int n = i >> 11, k = i & 2047;
    g_Wt[k*HIDN + n] = Wsoc[i];
  }
}

// ---------------- mask + bucketed neighbor lists + active bitmask (R0-proven) ----------------
__global__ void k_mask(const float* __restrict__ x, int t, int pred){
  __shared__ float spid[Psz], spx[Psz], spy[Psz];
  __shared__ unsigned char garr[Psz];
  __shared__ int cnt[G2N], off[G2N+1];
  int p = blockIdx.x, q = threadIdx.x;
  if (pred){
    spid[q] = x[((size_t)(Ssz-1)*Psz + q)*3 + 0];
    spx[q]  = g_o[(q*Bsz + 0)*OUTN + 0];
    spy[q]  = g_o[(q*Bsz + 0)*OUTN + 1];
  } else {
    const float* xb = x + (size_t)(t*Psz)*3;
    spid[q] = xb[q*3+0]; spx[q] = xb[q*3+1]; spy[q] = xb[q*3+2];
  }
  __syncthreads();
  const float Rx = 0.2f, Ry = 0.2f, CELLF = 0.1f;
  float lx = spx[p]-Rx, rxb = spx[p]+Rx, by = spy[p]-Ry, ty = spy[p]+Ry;
  float ox = spx[q], oy = spy[q];
  bool inb   = (ox < rxb) && (ox >= lx) && (oy < ty) && (oy >= by);
  bool valid = (spid[p] != 0.f) && (spid[q] != 0.f) && (spid[p] != spid[q]);
  int cx = (int)floorf((ox - lx)/CELLF);
  int cy = (int)floorf((oy - by)/CELLF);
  int idx = cx + cy*4; idx = idx < 0 ? 0 : (idx > 15 ? 15 : idx);
  garr[q] = (inb && valid) ? (unsigned char)idx : (unsigned char)255;
  __syncthreads();
  if (q < G2N){
    int c = 0;
    for (int o = 0; o < Psz; o++) if (garr[o] == (unsigned char)q) c++;
    cnt[q] = c;
  }
  __syncthreads();
  if (q == 0){
    int s = 0; unsigned int act = 0;
    for (int g = 0; g < G2N; g++){ off[g] = s; if (cnt[g]) act |= (1u<<g); s += cnt[g]; }
    off[G2N] = s;
    g_active[p] = act;
    for (int g = 0; g <= G2N; g++) g_off[p*(G2N+1)+g] = off[g];
  }
  __syncthreads();
  if (q < G2N){
    int w = off[q];
    for (int o = 0; o < Psz; o++)
      if (garr[o] == (unsigned char)q) g_list[p*Psz + (w++)] = (unsigned char)o;
  }
}

// ---------------- fused hsum-build + soc GEMM + e, writes z = [e|a] ----------------
// Block = (b, 64-p tile), 256 threads, 8 warps, 8x4 accum/thread.
// W read directly from pre-transposed g_Wt (L1-broadcast) — no smem staging,
// no per-kc syncs. FFMA order identical to the proven trajectory.
#define PT     64
#define HS_STR 132
__global__ void __launch_bounds__(256, 1) k_fused(
    const float* __restrict__ x,
    const float* __restrict__ bsoc,
    const float* __restrict__ Win,
    const float* __restrict__ bin,
    int t, int pred){
  extern __shared__ float dyn[];
  float* cs = dyn;                       // 256*128 floats = 128 KB
  float* hs = dyn + Psz*HIDN;            // 64*132 floats
  __shared__ unsigned char ls[PT*Psz];   // 16 KB neighbor lists
  __shared__ int offs[PT*(G2N+1)];
  __shared__ int gl[G2N];
  __shared__ int s_ng;

  int b = blockIdx.x, pbase = blockIdx.y*PT;
  int tid = threadIdx.x;
  float4* cs4 = (float4*)cs;

  // load c[:,b,:] (all 256 p rows for this b)
  for (int i = tid; i < Psz*HIDN/4; i += 256){
    int o = i>>5, q = i&31;
    cs4[i] = *(const float4*)(g_c + ((size_t)o*Bsz + b)*HIDN + q*4);
  }
  // neighbor lists + offsets for this p-tile (contiguous copy)
  for (int i = tid; i < PT*Psz/16; i += 256)
    ((uint4*)ls)[i] = ((const uint4*)(g_list + (size_t)pbase*Psz))[i];
  for (int i = tid; i < PT*(G2N+1); i += 256)
    offs[i] = g_off[pbase*(G2N+1) + i];
  if (tid == 0){
    unsigned int u = 0;
    for (int pp = 0; pp < PT; pp++) u |= g_active[pbase+pp];
    int n = 0;
    for (int g = 0; g < G2N; g++) if ((u>>g)&1u) gl[n++] = g;
    s_ng = n;
  }
  __syncthreads();
  int ng = s_ng;

  int tx = tid & 31, ty = tid >> 5;     // 8 warps
  int n0 = tx*4, m0 = ty*8;
  float acc[8][4];
  #pragma unroll
  for (int i = 0; i < 8; i++){
    #pragma unroll
    for (int j = 0; j < 4; j++) acc[i][j] = 0.f;
  }

  for (int gi = 0; gi < ng; gi++){
    int g = gl[gi];
    // ---- hsum tile [64 p][128 f]: EXACT dual-accumulator even/odd order ----
    #pragma unroll
    for (int i2 = 0; i2 < 8; i2++){
      int pl = ty*8 + i2;
      int s = offs[pl*17 + g], e = offs[pl*17 + g + 1];
      float4 a0 = make_float4(0.f,0.f,0.f,0.f);
      float4 a1 = make_float4(0.f,0.f,0.f,0.f);
      int j = s;
      for (; j+1 < e; j += 2){
        float4 v0 = cs4[(int)ls[pl*Psz + j]*32 + tx];
        float4 v1 = cs4[(int)ls[pl*Psz + j+1]*32 + tx];
        a0.x += v0.x; a0.y += v0.y; a0.z += v0.z; a0.w += v0.w;
        a1.x += v1.x; a1.y += v1.y; a1.z += v1.z; a1.w += v1.w;
      }
      if (j < e){
        float4 v0 = cs4[(int)ls[pl*Psz + j]*32 + tx];
        a0.x += v0.x; a0.y += v0.y; a0.z += v0.z; a0.w += v0.w;
      }
      float4 r;
      r.x = a0.x + a1.x; r.y = a0.y + a1.y;
      r.z = a0.z + a1.z; r.w = a0.w + a1.w;
      *(float4*)(hs + pl*HS_STR + tx*4) = r;
    }
    __syncthreads();                      // hs ready
    // ---- GEMM over this g's K=128: W straight from g_Wt (L1), no staging ----
    const float* Wg = g_Wt + (size_t)g*128*HIDN + n0;
    #pragma unroll 2
    for (int kc = 0; kc < 8; kc++){
      #pragma unroll
      for (int kq = 0; kq < 4; kq++){
        float4 hv[8];
        #pragma unroll
        for (int i = 0; i < 8; i++)
          hv[i] = *(const float4*)(hs + (m0+i)*HS_STR + kc*16 + kq*4);
        #pragma unroll
        for (int kk = 0; kk < 4; kk++){
          float4 w = *(const float4*)(Wg + (size_t)(kc*16 + kq*4 + kk)*HIDN);
          #pragma unroll
          for (int i = 0; i < 8; i++){
            float h = ((const float*)&hv[i])[kk];
            acc[i][0] += h*w.x; acc[i][1] += h*w.y;
            acc[i][2] += h*w.z; acc[i][3] += h*w.w;
          }
        }
      }
    }
    __syncthreads();                      // protect hs before next build
  }

  // ---- epilogue: a = relu(acc + b_soc) -> z[:,64:192] ----
  float4 bv = *(const float4*)(bsoc + n0);
  #pragma unroll
  for (int i = 0; i < 8; i++){
    int r = (pbase + m0 + i)*Bsz + b;
    float4 o;
    o.x = fmaxf(acc[i][0] + bv.x, 0.f);
    o.y = fmaxf(acc[i][1] + bv.y, 0.f);
    o.z = fmaxf(acc[i][2] + bv.z, 0.f);
    o.w = fmaxf(acc[i][3] + bv.w, 0.f);
    *(float4*)(g_z + (size_t)r*ZC + MIDN + n0) = o;
  }
  // ---- e = relu(pos @ Win^T + bin) -> z[:,0:64] ----
  for (int i2 = tid; i2 < PT*MIDN; i2 += 256){
    int mm = i2 >> 6, j = i2 & 63;
    int p = pbase + mm;
    int r = p*Bsz + b;
    float px, py;
    if (pred){ px = g_o[r*OUTN+0]; py = g_o[r*OUTN+1]; }
    else {
      const float* xr = x + (size_t)(((b*Ssz)+t)*Psz + p)*3;
      px = xr[1]; py = xr[2];
    }
    float v = px*Win[j*2+0] + py*Win[j*2+1] + bin[j];
    g_z[(size_t)r*ZC + j] = v > 0.f ? v : 0.f;
  }
}

// ---------------- LSTM gates (i,g,o only; f is dead) -> c, h ----------------
__global__ void k_lstm(const float* __restrict__ Wih,
                       const float* __restrict__ bih,
                       const float* __restrict__ bhh){
  __shared__ float Zs[16][68];
  __shared__ float Wg3[3][16][36];
  int mt = blockIdx.x, jt = blockIdx.y;
  int r0 = mt*64, j0 = jt*32;
  int tI = threadIdx.x;
  int tx = tI & 31, ty = tI >> 5;
  int m0 = ty*8;
  float ai[8], ag[8], ao[8];
  #pragma unroll
  for (int i = 0; i < 8; i++){ ai[i]=0.f; ag[i]=0.f; ao[i]=0.f; }
  int lm = tI >> 2, lk = (tI & 3)*4;
  for (int kc = 0; kc < 12; kc++){
    int kb = kc*16;
    float4 zv = *(const float4*)(g_z + (size_t)(r0+lm)*ZC + kb + lk);
    float4 wv[2]; int wg[2], wj[2], wk[2]; bool wval[2];
    #pragma unroll
    for (int i = 0; i < 2; i++){
      int idx = tI + i*256; wval[i] = idx < 384;
      wg[i]=0; wj[i]=0; wk[i]=0;
      if (wval[i]){
        wg[i] = idx/128; int rs = idx%128; wj[i] = rs>>2; wk[i] = (rs&3)*4;
        int baser = (wg[i]==0?0:(wg[i]==1?256:384)) + j0 + wj[i];
        wv[i] = *(const float4*)(Wih + (size_t)baser*ZC + kb + wk[i]);
      }
    }
    __syncthreads();
    Zs[lk+0][lm]=zv.x; Zs[lk+1][lm]=zv.y; Zs[lk+2][lm]=zv.z; Zs[lk+3][lm]=zv.w;
    #pragma unroll
    for (int i = 0; i < 2; i++){
      if (wval[i]){
        Wg3[wg[i]][wk[i]+0][wj[i]]=wv[i].x; Wg3[wg[i]][wk[i]+1][wj[i]]=wv[i].y;
        Wg3[wg[i]][wk[i]+2][wj[i]]=wv[i].z; Wg3[wg[i]][wk[i]+3][wj[i]]=wv[i].w;
      }
    }
    __syncthreads();
    #pragma unroll
    for (int kk = 0; kk < 16; kk++){
      float4 z0 = *(const float4*)(&Zs[kk][m0]);
      float4 z1 = *(const float4*)(&Zs[kk][m0+4]);
      float zz[8] = {z0.x,z0.y,z0.z,z0.w,z1.x,z1.y,z1.z,z1.w};
      float wi = Wg3[0][kk][tx], wgg = Wg3[1][kk][tx], wo = Wg3[2][kk][tx];
      #pragma unroll
      for (int i = 0; i < 8; i++){
        ai[i] += zz[i]*wi; ag[i] += zz[i]*wgg; ao[i] += zz[i]*wo;
      }
    }
    __syncthreads();
  }
  int j = j0 + tx;
  float bi_ = bih[j]       + bhh[j];
  float bg_ = bih[256 + j] + bhh[256 + j];
  float bo_ = bih[384 + j] + bhh[384 + j];
  #pragma unroll
  for (int i = 0; i < 8; i++){
    int r = r0 + m0 + i;
    float ci = sigf(ai[i]+bi_)*tanhf(ag[i]+bg_);
    float hh = sigf(ao[i]+bo_)*tanhf(ci);
    g_c[(size_t)r*HIDN + j] = ci;
    g_h[(size_t)r*HIDN + j] = hh;
  }
}

// ---------------- output head o = h @ Wout^T + bout (+ op write, + xp write) ----------------
__global__ void k_out(const float* __restrict__ Wout, const float* __restrict__ bout,
                      const float* __restrict__ x, float* __restrict__ out,
                      int wr_op, int kstep, int wr_xp, int xpk){
  int warp = threadIdx.x >> 5, lane = threadIdx.x & 31;
  int r = blockIdx.x*8 + warp;
  float hv[4];
  #pragma unroll
  for (int i = 0; i < 4; i++) hv[i] = g_h[(size_t)r*HIDN + lane + i*32];
  float res[5];
  #pragma unroll
  for (int c = 0; c < 5; c++){
    float s = 0.f;
    #pragma unroll
    for (int i = 0; i < 4; i++) s += hv[i]*__ldg(Wout + c*HIDN + lane + i*32);
    #pragma unroll
    for (int d = 16; d > 0; d >>= 1) s += __shfl_xor_sync(0xffffffffu, s, d);
    res[c] = s + bout[c];
  }
  if (lane == 0){
    int b = r & 31, p = r >> 5;
    #pragma unroll
    for (int c = 0; c < 5; c++){
      g_o[r*OUTN + c] = res[c];
      if (wr_op)
        out[(size_t)XP_ELEMS + ((size_t)(b*PREDN + kstep)*Psz + p)*OUTN + c] = res[c];
    }
    if (wr_xp){
      float pid = x[((size_t)(b*Ssz + Ssz-1)*Psz + p)*3 + 0];
      size_t base = ((size_t)(b*PREDN + xpk)*Psz + p)*3;
      out[base+0] = pid;
      out[base+1] = res[0];
      out[base+2] = res[1];
    }
  }
}

// ---------------- launch ----------------
extern "C" void kernel_launch(void* const* d_in, const int* in_sizes, int n_in,
                              void* d_out, int out_size){
  const float* x    = (const float*)d_in[0];
  const float* Win  = (const float*)d_in[1];
  const float* bin  = (const float*)d_in[2];
  const float* Wsoc = (const float*)d_in[3];
  const float* bsoc = (const float*)d_in[4];
  const float* bprev= (const float*)d_in[5];
  const float* Wih  = (const float*)d_in[6];
  const float* bih  = (const float*)d_in[7];
  const float* bhh  = (const float*)d_in[8];
  const float* Wout = (const float*)d_in[9];
  const float* bout = (const float*)d_in[10];
  float* out = (float*)d_out;

  const int DYN = (Psz*HIDN + PT*HS_STR)*(int)sizeof(float);
  cudaFuncSetAttribute(k_fused, cudaFuncAttributeMaxDynamicSharedMemorySize, DYN);

  k_init<<<(RROWS*HIDN + 255)/256, 256>>>(bprev);
  k_wt<<<(HIDN*2048 + 255)/256, 256>>>(Wsoc);
  for (int t = 0; t < OBSN; t++){
    k_mask<<<Psz, Psz>>>(x, t, 0);
    k_fused<<<dim3(Bsz, Psz/PT), 256, DYN>>>(x, bsoc, Win, bin, t, 0);
    k_lstm<<<dim3(RROWS/64, 4), 256>>>(Wih, bih, bhh);
    if (t == OBSN-1)
      k_out<<<RROWS/8, 256>>>(Wout, bout, x, out, 0, 0, 1, 0);   // g_o + xp[0]
  }
  for (int k = 0; k < PREDN; k++){
    k_mask<<<Psz, Psz>>>(x, 0, 1);
    k_fused<<<dim3(Bsz, Psz/PT), 256, DYN>>>(x, bsoc, Win, bin, 0, 1);
    k_lstm<<<dim3(RROWS/64, 4), 256>>>(Wih, bih, bhh);
    k_out<<<RROWS/8, 256>>>(Wout, bout, x, out, 1, k, (k < PREDN-1) ? 1 : 0, k+1);
  }
}

// round 8
// speedup vs baseline: 1.1843x; 1.0564x over previous
#include <cuda_runtime.h>
#include <math.h>

#define Bsz   32
#define Ssz   20
#define Psz   256
#define HIDN  128
#define MIDN  64
#define G2N   16
#define OBSN  8
#define PREDN 12
#define OUTN  5
#define RROWS (Psz*Bsz)          // 8192 rows, r = p*32 + b  (p-major)
#define ZC    (MIDN+HIDN)        // 192
#define XP_ELEMS (Bsz*PREDN*Psz*3)   // 294912

// ---- packed fp32x2 helpers (sm_100+): bit-exact per-lane fma.rn.f32 ----
#define PACK2(d, s)      asm("mov.b64 %0, {%1, %1};" : "=l"(d) : "f"(s))
#define UNPACK2(lo,hi,s) asm("mov.b64 {%0, %1}, %2;" : "=f"(lo), "=f"(hi) : "l"(s))
#define FMA2(d, a, b)    asm("fma.rn.f32x2 %0, %1, %2, %0;" : "+l"(d) : "l"(a), "l"(b))

// ---------------- device scratch ----------------
__device__ float g_c[RROWS*HIDN];          // carry (cell state), 4 MB
__device__ float g_z[RROWS*ZC];            // [e | a], 6 MB
__device__ float g_h[RROWS*HIDN];          // hidden h, 4 MB
__device__ float g_o[RROWS*OUTN];          // last output
__device__ float g_Wt[2048*HIDN];          // W_soc transposed [k][n], 1 MB
__device__ unsigned char g_list[Psz*Psz];  // per-p neighbor ids grouped by cell
__device__ int g_off[Psz*(G2N+1)];         // per-p per-cell offsets
__device__ unsigned int g_active[Psz];     // per-p active-cell bitmask

__device__ __forceinline__ float sigf(float x){ return 1.f/(1.f+expf(-x)); }

// ---------------- init carry = relu(b_prev) broadcast ----------------
__global__ void k_init(const float* __restrict__ bprev){
  int i = blockIdx.x*256 + threadIdx.x;
  if (i < RROWS*HIDN){ float v = bprev[i & (HIDN-1)]; g_c[i] = v > 0.f ? v : 0.f; }
}

// ---------------- one-time transpose of W_soc [128][2048] -> g_Wt [2048][128] ----------------
__global__ void k_wt(const float* __restrict__ Wsoc){
  int i = blockIdx.x*256 + threadIdx.x;     // i over 128*2048
  if (i < HIDN*2048){
    int n = i >> 11, k = i & 2047;
    g_Wt[k*HIDN + n] = Wsoc[i];
  }
}

// ---------------- mask + bucketed neighbor lists + active bitmask (R0-proven) ----------------
__global__ void k_mask(const float* __restrict__ x, int t, int pred){
  __shared__ float spid[Psz], spx[Psz], spy[Psz];
  __shared__ unsigned char garr[Psz];
  __shared__ int cnt[G2N], off[G2N+1];
  int p = blockIdx.x, q = threadIdx.x;
  if (pred){
    spid[q] = x[((size_t)(Ssz-1)*Psz + q)*3 + 0];
    spx[q]  = g_o[(q*Bsz + 0)*OUTN + 0];
    spy[q]  = g_o[(q*Bsz + 0)*OUTN + 1];
  } else {
    const float* xb = x + (size_t)(t*Psz)*3;
    spid[q] = xb[q*3+0]; spx[q] = xb[q*3+1]; spy[q] = xb[q*3+2];
  }
  __syncthreads();
  const float Rx = 0.2f, Ry = 0.2f, CELLF = 0.1f;
  float lx = spx[p]-Rx, rxb = spx[p]+Rx, by = spy[p]-Ry, ty = spy[p]+Ry;
  float ox = spx[q], oy = spy[q];
  bool inb   = (ox < rxb) && (ox >= lx) && (oy < ty) && (oy >= by);
  bool valid = (spid[p] != 0.f) && (spid[q] != 0.f) && (spid[p] != spid[q]);
  int cx = (int)floorf((ox - lx)/CELLF);
  int cy = (int)floorf((oy - by)/CELLF);
  int idx = cx + cy*4; idx = idx < 0 ? 0 : (idx > 15 ? 15 : idx);
  garr[q] = (inb && valid) ? (unsigned char)idx : (unsigned char)255;
  __syncthreads();
  if (q < G2N){
    int c = 0;
    for (int o = 0; o < Psz; o++) if (garr[o] == (unsigned char)q) c++;
    cnt[q] = c;
  }
  __syncthreads();
  if (q == 0){
    int s = 0; unsigned int act = 0;
    for (int g = 0; g < G2N; g++){ off[g] = s; if (cnt[g]) act |= (1u<<g); s += cnt[g]; }
    off[G2N] = s;
    g_active[p] = act;
    for (int g = 0; g <= G2N; g++) g_off[p*(G2N+1)+g] = off[g];
  }
  __syncthreads();
  if (q < G2N){
    int w = off[q];
    for (int o = 0; o < Psz; o++)
      if (garr[o] == (unsigned char)q) g_list[p*Psz + (w++)] = (unsigned char)o;
  }
}

// ---------------- fused hsum-build + soc GEMM (FFMA2) + e, writes z = [e|a] ----------------
// Block = (b, 64-p tile), 256 threads, 8 warps, 8x4 accum/thread.
// GEMM packed: acc pairs along n (cols) — w pairs free from 128-bit loads,
// h duplicated via mov.b64. Per-element fma.rn chains identical to R7.
#define PT     64
#define HS_STR 132
__global__ void __launch_bounds__(256, 1) k_fused(
    const float* __restrict__ x,
    const float* __restrict__ bsoc,
    const float* __restrict__ Win,
    const float* __restrict__ bin,
    int t, int pred){
  extern __shared__ float dyn[];
  float* cs = dyn;                       // 256*128 floats = 128 KB
  float* hs = dyn + Psz*HIDN;            // 64*132 floats
  __shared__ unsigned char ls[PT*Psz];   // 16 KB neighbor lists
  __shared__ int offs[PT*(G2N+1)];
  __shared__ int gl[G2N];
  __shared__ int s_ng;

  int b = blockIdx.x, pbase = blockIdx.y*PT;
  int tid = threadIdx.x;
  float4* cs4 = (float4*)cs;

  // load c[:,b,:] (all 256 p rows for this b)
  for (int i = tid; i < Psz*HIDN/4; i += 256){
    int o = i>>5, q = i&31;
    cs4[i] = *(const float4*)(g_c + ((size_t)o*Bsz + b)*HIDN + q*4);
  }
  // neighbor lists + offsets for this p-tile (contiguous copy)
  for (int i = tid; i < PT*Psz/16; i += 256)
    ((uint4*)ls)[i] = ((const uint4*)(g_list + (size_t)pbase*Psz))[i];
  for (int i = tid; i < PT*(G2N+1); i += 256)
    offs[i] = g_off[pbase*(G2N+1) + i];
  if (tid == 0){
    unsigned int u = 0;
    for (int pp = 0; pp < PT; pp++) u |= g_active[pbase+pp];
    int n = 0;
    for (int g = 0; g < G2N; g++) if ((u>>g)&1u) gl[n++] = g;
    s_ng = n;
  }
  __syncthreads();
  int ng = s_ng;

  int tx = tid & 31, ty = tid >> 5;     // 8 warps
  int n0 = tx*4, m0 = ty*8;
  unsigned long long acc01[8], acc23[8];
  #pragma unroll
  for (int i = 0; i < 8; i++){ acc01[i] = 0ull; acc23[i] = 0ull; }

  for (int gi = 0; gi < ng; gi++){
    int g = gl[gi];
    // ---- hsum tile [64 p][128 f]: EXACT dual-accumulator even/odd order ----
    #pragma unroll
    for (int i2 = 0; i2 < 8; i2++){
      int pl = ty*8 + i2;
      int s = offs[pl*17 + g], e = offs[pl*17 + g + 1];
      float4 a0 = make_float4(0.f,0.f,0.f,0.f);
      float4 a1 = make_float4(0.f,0.f,0.f,0.f);
      int j = s;
      for (; j+1 < e; j += 2){
        float4 v0 = cs4[(int)ls[pl*Psz + j]*32 + tx];
        float4 v1 = cs4[(int)ls[pl*Psz + j+1]*32 + tx];
        a0.x += v0.x; a0.y += v0.y; a0.z += v0.z; a0.w += v0.w;
        a1.x += v1.x; a1.y += v1.y; a1.z += v1.z; a1.w += v1.w;
      }
      if (j < e){
        float4 v0 = cs4[(int)ls[pl*Psz + j]*32 + tx];
        a0.x += v0.x; a0.y += v0.y; a0.z += v0.z; a0.w += v0.w;
      }
      float4 r;
      r.x = a0.x + a1.x; r.y = a0.y + a1.y;
      r.z = a0.z + a1.z; r.w = a0.w + a1.w;
      *(float4*)(hs + pl*HS_STR + tx*4) = r;
    }
    __syncthreads();                      // hs ready
    // ---- GEMM over this g's K=128 with packed FFMA2 ----
    const float* Wg = g_Wt + (size_t)g*128*HIDN + n0;
    #pragma unroll 2
    for (int kc = 0; kc < 8; kc++){
      #pragma unroll
      for (int kq = 0; kq < 4; kq++){
        float4 hv[8];
        #pragma unroll
        for (int i = 0; i < 8; i++)
          hv[i] = *(const float4*)(hs + (m0+i)*HS_STR + kc*16 + kq*4);
        #pragma unroll
        for (int kk = 0; kk < 4; kk++){
          ulonglong2 wp = *(const ulonglong2*)(Wg + (size_t)(kc*16 + kq*4 + kk)*HIDN);
          #pragma unroll
          for (int i = 0; i < 8; i++){
            float h = ((const float*)&hv[i])[kk];
            unsigned long long h2;
            PACK2(h2, h);
            FMA2(acc01[i], h2, wp.x);
            FMA2(acc23[i], h2, wp.y);
          }
        }
      }
    }
    __syncthreads();                      // protect hs before next build
  }

  // ---- epilogue: a = relu(acc + b_soc) -> z[:,64:192] ----
  float4 bv = *(const float4*)(bsoc + n0);
  #pragma unroll
  for (int i = 0; i < 8; i++){
    int r = (pbase + m0 + i)*Bsz + b;
    float a0, a1, a2, a3;
    UNPACK2(a0, a1, acc01[i]);
    UNPACK2(a2, a3, acc23[i]);
    float4 o;
    o.x = fmaxf(a0 + bv.x, 0.f);
    o.y = fmaxf(a1 + bv.y, 0.f);
    o.z = fmaxf(a2 + bv.z, 0.f);
    o.w = fmaxf(a3 + bv.w, 0.f);
    *(float4*)(g_z + (size_t)r*ZC + MIDN + n0) = o;
  }
  // ---- e = relu(pos @ Win^T + bin) -> z[:,0:64] ----
  for (int i2 = tid; i2 < PT*MIDN; i2 += 256){
    int mm = i2 >> 6, j = i2 & 63;
    int p = pbase + mm;
    int r = p*Bsz + b;
    float px, py;
    if (pred){ px = g_o[r*OUTN+0]; py = g_o[r*OUTN+1]; }
    else {
      const float* xr = x + (size_t)(((b*Ssz)+t)*Psz + p)*3;
      px = xr[1]; py = xr[2];
    }
    float v = px*Win[j*2+0] + py*Win[j*2+1] + bin[j];
    g_z[(size_t)r*ZC + j] = v > 0.f ? v : 0.f;
  }
}

// ---------------- LSTM gates (i,g,o only; f is dead) -> c, h  (FFMA2 row-pairs) ----------------
__global__ void k_lstm(const float* __restrict__ Wih,
                       const float* __restrict__ bih,
                       const float* __restrict__ bhh){
  __shared__ float Zs[16][68];
  __shared__ float Wg3[3][16][36];
  int mt = blockIdx.x, jt = blockIdx.y;
  int r0 = mt*64, j0 = jt*32;
  int tI = threadIdx.x;
  int tx = tI & 31, ty = tI >> 5;
  int m0 = ty*8;
  unsigned long long ai2[4], ag2[4], ao2[4];
  #pragma unroll
  for (int i = 0; i < 4; i++){ ai2[i]=0ull; ag2[i]=0ull; ao2[i]=0ull; }
  int lm = tI >> 2, lk = (tI & 3)*4;
  for (int kc = 0; kc < 12; kc++){
    int kb = kc*16;
    float4 zv = *(const float4*)(g_z + (size_t)(r0+lm)*ZC + kb + lk);
    float4 wv[2]; int wg[2], wj[2], wk[2]; bool wval[2];
    #pragma unroll
    for (int i = 0; i < 2; i++){
      int idx = tI + i*256; wval[i] = idx < 384;
      wg[i]=0; wj[i]=0; wk[i]=0;
      if (wval[i]){
        wg[i] = idx/128; int rs = idx%128; wj[i] = rs>>2; wk[i] = (rs&3)*4;
        int baser = (wg[i]==0?0:(wg[i]==1?256:384)) + j0 + wj[i];
        wv[i] = *(const float4*)(Wih + (size_t)baser*ZC + kb + wk[i]);
      }
    }
    __syncthreads();
    Zs[lk+0][lm]=zv.x; Zs[lk+1][lm]=zv.y; Zs[lk+2][lm]=zv.z; Zs[lk+3][lm]=zv.w;
    #pragma unroll
    for (int i = 0; i < 2; i++){
      if (wval[i]){
        Wg3[wg[i]][wk[i]+0][wj[i]]=wv[i].x; Wg3[wg[i]][wk[i]+1][wj[i]]=wv[i].y;
        Wg3[wg[i]][wk[i]+2][wj[i]]=wv[i].z; Wg3[wg[i]][wk[i]+3][wj[i]]=wv[i].w;
      }
    }
    __syncthreads();
    #pragma unroll
    for (int kk = 0; kk < 16; kk++){
      // z row-pairs packed free via 128-bit loads (16B-aligned: m0 multiple of 8)
      ulonglong2 zp0 = *(const ulonglong2*)(&Zs[kk][m0]);
      ulonglong2 zp1 = *(const ulonglong2*)(&Zs[kk][m0+4]);
      float wi = Wg3[0][kk][tx], wgg = Wg3[1][kk][tx], wo = Wg3[2][kk][tx];
      unsigned long long wi2, wg2v, wo2;
      PACK2(wi2, wi); PACK2(wg2v, wgg); PACK2(wo2, wo);
      FMA2(ai2[0], zp0.x, wi2);  FMA2(ai2[1], zp0.y, wi2);
      FMA2(ai2[2], zp1.x, wi2);  FMA2(ai2[3], zp1.y, wi2);
      FMA2(ag2[0], zp0.x, wg2v); FMA2(ag2[1], zp0.y, wg2v);
      FMA2(ag2[2], zp1.x, wg2v); FMA2(ag2[3], zp1.y, wg2v);
      FMA2(ao2[0], zp0.x, wo2);  FMA2(ao2[1], zp0.y, wo2);
      FMA2(ao2[2], zp1.x, wo2);  FMA2(ao2[3], zp1.y, wo2);
    }
    __syncthreads();
  }
  float ai[8], ag[8], ao[8];
  #pragma unroll
  for (int i = 0; i < 4; i++){
    UNPACK2(ai[2*i], ai[2*i+1], ai2[i]);
    UNPACK2(ag[2*i], ag[2*i+1], ag2[i]);
    UNPACK2(ao[2*i], ao[2*i+1], ao2[i]);
  }
  int j = j0 + tx;
  float bi_ = bih[j]       + bhh[j];
  float bg_ = bih[256 + j] + bhh[256 + j];
  float bo_ = bih[384 + j] + bhh[384 + j];
  #pragma unroll
  for (int i = 0; i < 8; i++){
    int r = r0 + m0 + i;
    float ci = sigf(ai[i]+bi_)*tanhf(ag[i]+bg_);
    float hh = sigf(ao[i]+bo_)*tanhf(ci);
    g_c[(size_t)r*HIDN + j] = ci;
    g_h[(size_t)r*HIDN + j] = hh;
  }
}

// ---------------- output head o = h @ Wout^T + bout (+ op write, + xp write) ----------------
__global__ void k_out(const float* __restrict__ Wout, const float* __restrict__ bout,
                      const float* __restrict__ x, float* __restrict__ out,
                      int wr_op, int kstep, int wr_xp, int xpk){
  int warp = threadIdx.x >> 5, lane = threadIdx.x & 31;
  int r = blockIdx.x*8 + warp;
  float hv[4];
  #pragma unroll
  for (int i = 0; i < 4; i++) hv[i] = g_h[(size_t)r*HIDN + lane + i*32];
  float res[5];
  #pragma unroll
  for (int c = 0; c < 5; c++){
    float s = 0.f;
    #pragma unroll
    for (int i = 0; i < 4; i++) s += hv[i]*__ldg(Wout + c*HIDN + lane + i*32);
    #pragma unroll
    for (int d = 16; d > 0; d >>= 1) s += __shfl_xor_sync(0xffffffffu, s, d);
    res[c] = s + bout[c];
  }
  if (lane == 0){
    int b = r & 31, p = r >> 5;
    #pragma unroll
    for (int c = 0; c < 5; c++){
      g_o[r*OUTN + c] = res[c];
      if (wr_op)
        out[(size_t)XP_ELEMS + ((size_t)(b*PREDN + kstep)*Psz + p)*OUTN + c] = res[c];
    }
    if (wr_xp){
      float pid = x[((size_t)(b*Ssz + Ssz-1)*Psz + p)*3 + 0];
      size_t base = ((size_t)(b*PREDN + xpk)*Psz + p)*3;
      out[base+0] = pid;
      out[base+1] = res[0];
      out[base+2] = res[1];
    }
  }
}

// ---------------- launch ----------------
extern "C" void kernel_launch(void* const* d_in, const int* in_sizes, int n_in,
                              void* d_out, int out_size){
  const float* x    = (const float*)d_in[0];
  const float* Win  = (const float*)d_in[1];
  const float* bin  = (const float*)d_in[2];
  const float* Wsoc = (const float*)d_in[3];
  const float* bsoc = (const float*)d_in[4];
  const float* bprev= (const float*)d_in[5];
  const float* Wih  = (const float*)d_in[6];
  const float* bih  = (const float*)d_in[7];
  const float* bhh  = (const float*)d_in[8];
  const float* Wout = (const float*)d_in[9];
  const float* bout = (const float*)d_in[10];
  float* out = (float*)d_out;

  const int DYN = (Psz*HIDN + PT*HS_STR)*(int)sizeof(float);
  cudaFuncSetAttribute(k_fused, cudaFuncAttributeMaxDynamicSharedMemorySize, DYN);

  k_init<<<(RROWS*HIDN + 255)/256, 256>>>(bprev);
  k_wt<<<(HIDN*2048 + 255)/256, 256>>>(Wsoc);
  for (int t = 0; t < OBSN; t++){
    k_mask<<<Psz, Psz>>>(x, t, 0);
    k_fused<<<dim3(Bsz, Psz/PT), 256, DYN>>>(x, bsoc, Win, bin, t, 0);
    k_lstm<<<dim3(RROWS/64, 4), 256>>>(Wih, bih, bhh);
    if (t == OBSN-1)
      k_out<<<RROWS/8, 256>>>(Wout, bout, x, out, 0, 0, 1, 0);   // g_o + xp[0]
  }
  for (int k = 0; k < PREDN; k++){
    k_mask<<<Psz, Psz>>>(x, 0, 1);
    k_fused<<<dim3(Bsz, Psz/PT), 256, DYN>>>(x, bsoc, Win, bin, 0, 1);
    k_lstm<<<dim3(RROWS/64, 4), 256>>>(Wih, bih, bhh);
    k_out<<<RROWS/8, 256>>>(Wout, bout, x, out, 1, k, (k < PREDN-1) ? 1 : 0, k+1);
  }
}

// round 9
// speedup vs baseline: 1.2453x; 1.0515x over previous
#include <cuda_runtime.h>
#include <math.h>

#define Bsz   32
#define Ssz   20
#define Psz   256
#define HIDN  128
#define MIDN  64
#define G2N   16
#define OBSN  8
#define PREDN 12
#define OUTN  5
#define RROWS (Psz*Bsz)          // 8192 rows, r = p*32 + b  (p-major)
#define ZC    (MIDN+HIDN)        // 192
#define XP_ELEMS (Bsz*PREDN*Psz*3)   // 294912

// ---- packed fp32x2 helpers (sm_100+): bit-exact per-lane f32 ops ----
#define PACK2(d, s)      asm("mov.b64 %0, {%1, %1};" : "=l"(d) : "f"(s))
#define UNPACK2(lo,hi,s) asm("mov.b64 {%0, %1}, %2;" : "=f"(lo), "=f"(hi) : "l"(s))
#define FMA2(d, a, b)    asm("fma.rn.f32x2 %0, %1, %2, %0;" : "+l"(d) : "l"(a), "l"(b))
#define ADD2(d, a)       asm("add.rn.f32x2 %0, %0, %1;" : "+l"(d) : "l"(a))

// ---------------- device scratch ----------------
__device__ float g_c[RROWS*HIDN];          // carry (cell state), 4 MB
__device__ float g_z[RROWS*ZC];            // [e | a], 6 MB
__device__ float g_h[RROWS*HIDN];          // hidden h, 4 MB
__device__ float g_o[RROWS*OUTN];          // last output
__device__ float g_Wt[2048*HIDN];          // W_soc transposed [k][n], 1 MB
__device__ unsigned char g_list[Psz*Psz];  // per-p neighbor ids grouped by cell
__device__ int g_off[Psz*(G2N+1)];         // per-p per-cell offsets
__device__ unsigned int g_active[Psz];     // per-p active-cell bitmask

__device__ __forceinline__ float sigf(float x){ return 1.f/(1.f+expf(-x)); }

// ---------------- init carry = relu(b_prev) broadcast ----------------
__global__ void k_init(const float* __restrict__ bprev){
  int i = blockIdx.x*256 + threadIdx.x;
  if (i < RROWS*HIDN){ float v = bprev[i & (HIDN-1)]; g_c[i] = v > 0.f ? v : 0.f; }
}

// ---------------- one-time transpose of W_soc [128][2048] -> g_Wt [2048][128] ----------------
__global__ void k_wt(const float* __restrict__ Wsoc){
  int i = blockIdx.x*256 + threadIdx.x;     // i over 128*2048
  if (i < HIDN*2048){
    int n = i >> 11, k = i & 2047;
    g_Wt[k*HIDN + n] = Wsoc[i];
  }
}

// ---------------- mask + bucketed neighbor lists + active bitmask (R0-proven) ----------------
__global__ void k_mask(const float* __restrict__ x, int t, int pred){
  __shared__ float spid[Psz], spx[Psz], spy[Psz];
  __shared__ unsigned char garr[Psz];
  __shared__ int cnt[G2N], off[G2N+1];
  int p = blockIdx.x, q = threadIdx.x;
  if (pred){
    spid[q] = x[((size_t)(Ssz-1)*Psz + q)*3 + 0];
    spx[q]  = g_o[(q*Bsz + 0)*OUTN + 0];
    spy[q]  = g_o[(q*Bsz + 0)*OUTN + 1];
  } else {
    const float* xb = x + (size_t)(t*Psz)*3;
    spid[q] = xb[q*3+0]; spx[q] = xb[q*3+1]; spy[q] = xb[q*3+2];
  }
  __syncthreads();
  const float Rx = 0.2f, Ry = 0.2f, CELLF = 0.1f;
  float lx = spx[p]-Rx, rxb = spx[p]+Rx, by = spy[p]-Ry, ty = spy[p]+Ry;
  float ox = spx[q], oy = spy[q];
  bool inb   = (ox < rxb) && (ox >= lx) && (oy < ty) && (oy >= by);
  bool valid = (spid[p] != 0.f) && (spid[q] != 0.f) && (spid[p] != spid[q]);
  int cx = (int)floorf((ox - lx)/CELLF);
  int cy = (int)floorf((oy - by)/CELLF);
  int idx = cx + cy*4; idx = idx < 0 ? 0 : (idx > 15 ? 15 : idx);
  garr[q] = (inb && valid) ? (unsigned char)idx : (unsigned char)255;
  __syncthreads();
  if (q < G2N){
    int c = 0;
    for (int o = 0; o < Psz; o++) if (garr[o] == (unsigned char)q) c++;
    cnt[q] = c;
  }
  __syncthreads();
  if (q == 0){
    int s = 0; unsigned int act = 0;
    for (int g = 0; g < G2N; g++){ off[g] = s; if (cnt[g]) act |= (1u<<g); s += cnt[g]; }
    off[G2N] = s;
    g_active[p] = act;
    for (int g = 0; g <= G2N; g++) g_off[p*(G2N+1)+g] = off[g];
  }
  __syncthreads();
  if (q < G2N){
    int w = off[q];
    for (int o = 0; o < Psz; o++)
      if (garr[o] == (unsigned char)q) g_list[p*Psz + (w++)] = (unsigned char)o;
  }
}

// ---------------- fused hsum-build + soc GEMM (all f32x2) + e, writes z = [e|a] ----------------
// Block = (b, 64-p tile), 256 threads, 8 warps, 8x4 accum/thread.
// hsum: dual accumulators packed as f32x2 component-pairs (per-component chains
// unchanged => bit-exact). GEMM: FFMA2, n-col pairs, h duplicated.
#define PT     64
#define HS_STR 132
__global__ void __launch_bounds__(256, 1) k_fused(
    const float* __restrict__ x,
    const float* __restrict__ bsoc,
    const float* __restrict__ Win,
    const float* __restrict__ bin,
    int t, int pred){
  extern __shared__ float dyn[];
  float* cs = dyn;                       // 256*128 floats = 128 KB
  float* hs = dyn + Psz*HIDN;            // 64*132 floats
  __shared__ unsigned char ls[PT*Psz];   // 16 KB neighbor lists
  __shared__ int offs[PT*(G2N+1)];
  __shared__ int gl[G2N];
  __shared__ int s_ng;

  int b = blockIdx.x, pbase = blockIdx.y*PT;
  int tid = threadIdx.x;
  float4* cs4 = (float4*)cs;

  // load c[:,b,:] (all 256 p rows for this b)
  for (int i = tid; i < Psz*HIDN/4; i += 256){
    int o = i>>5, q = i&31;
    cs4[i] = *(const float4*)(g_c + ((size_t)o*Bsz + b)*HIDN + q*4);
  }
  // neighbor lists + offsets for this p-tile (contiguous copy)
  for (int i = tid; i < PT*Psz/16; i += 256)
    ((uint4*)ls)[i] = ((const uint4*)(g_list + (size_t)pbase*Psz))[i];
  for (int i = tid; i < PT*(G2N+1); i += 256)
    offs[i] = g_off[pbase*(G2N+1) + i];
  if (tid == 0){
    unsigned int u = 0;
    for (int pp = 0; pp < PT; pp++) u |= g_active[pbase+pp];
    int n = 0;
    for (int g = 0; g < G2N; g++) if ((u>>g)&1u) gl[n++] = g;
    s_ng = n;
  }
  __syncthreads();
  int ng = s_ng;

  int tx = tid & 31, ty = tid >> 5;     // 8 warps
  int n0 = tx*4, m0 = ty*8;
  unsigned long long acc01[8], acc23[8];
  #pragma unroll
  for (int i = 0; i < 8; i++){ acc01[i] = 0ull; acc23[i] = 0ull; }

  for (int gi = 0; gi < ng; gi++){
    int g = gl[gi];
    // ---- hsum tile [64 p][128 f]: dual-accumulator even/odd order, f32x2 packed ----
    #pragma unroll
    for (int i2 = 0; i2 < 8; i2++){
      int pl = ty*8 + i2;
      int s = offs[pl*17 + g], e = offs[pl*17 + g + 1];
      unsigned long long a0lo = 0ull, a0hi = 0ull, a1lo = 0ull, a1hi = 0ull;
      int j = s;
      for (; j+1 < e; j += 2){
        ulonglong2 v0 = *(const ulonglong2*)(cs4 + (int)ls[pl*Psz + j]*32 + tx);
        ulonglong2 v1 = *(const ulonglong2*)(cs4 + (int)ls[pl*Psz + j+1]*32 + tx);
        ADD2(a0lo, v0.x); ADD2(a0hi, v0.y);
        ADD2(a1lo, v1.x); ADD2(a1hi, v1.y);
      }
      if (j < e){
        ulonglong2 v0 = *(const ulonglong2*)(cs4 + (int)ls[pl*Psz + j]*32 + tx);
        ADD2(a0lo, v0.x); ADD2(a0hi, v0.y);
      }
      ADD2(a0lo, a1lo); ADD2(a0hi, a1hi);
      *(ulonglong2*)(hs + pl*HS_STR + tx*4) = make_ulonglong2(a0lo, a0hi);
    }
    __syncthreads();                      // hs ready
    // ---- GEMM over this g's K=128 with packed FFMA2 ----
    const float* Wg = g_Wt + (size_t)g*128*HIDN + n0;
    #pragma unroll 4
    for (int kc = 0; kc < 8; kc++){
      #pragma unroll
      for (int kq = 0; kq < 4; kq++){
        float4 hv[8];
        #pragma unroll
        for (int i = 0; i < 8; i++)
          hv[i] = *(const float4*)(hs + (m0+i)*HS_STR + kc*16 + kq*4);
        #pragma unroll
        for (int kk = 0; kk < 4; kk++){
          ulonglong2 wp = *(const ulonglong2*)(Wg + (size_t)(kc*16 + kq*4 + kk)*HIDN);
          #pragma unroll
          for (int i = 0; i < 8; i++){
            float h = ((const float*)&hv[i])[kk];
            unsigned long long h2;
            PACK2(h2, h);
            FMA2(acc01[i], h2, wp.x);
            FMA2(acc23[i], h2, wp.y);
          }
        }
      }
    }
    __syncthreads();                      // protect hs before next build
  }

  // ---- epilogue: a = relu(acc + b_soc) -> z[:,64:192] ----
  float4 bv = *(const float4*)(bsoc + n0);
  #pragma unroll
  for (int i = 0; i < 8; i++){
    int r = (pbase + m0 + i)*Bsz + b;
    float a0, a1, a2, a3;
    UNPACK2(a0, a1, acc01[i]);
    UNPACK2(a2, a3, acc23[i]);
    float4 o;
    o.x = fmaxf(a0 + bv.x, 0.f);
    o.y = fmaxf(a1 + bv.y, 0.f);
    o.z = fmaxf(a2 + bv.z, 0.f);
    o.w = fmaxf(a3 + bv.w, 0.f);
    *(float4*)(g_z + (size_t)r*ZC + MIDN + n0) = o;
  }
  // ---- e = relu(pos @ Win^T + bin) -> z[:,0:64] ----
  for (int i2 = tid; i2 < PT*MIDN; i2 += 256){
    int mm = i2 >> 6, j = i2 & 63;
    int p = pbase + mm;
    int r = p*Bsz + b;
    float px, py;
    if (pred){ px = g_o[r*OUTN+0]; py = g_o[r*OUTN+1]; }
    else {
      const float* xr = x + (size_t)(((b*Ssz)+t)*Psz + p)*3;
      px = xr[1]; py = xr[2];
    }
    float v = px*Win[j*2+0] + py*Win[j*2+1] + bin[j];
    g_z[(size_t)r*ZC + j] = v > 0.f ? v : 0.f;
  }
}

// ---------------- LSTM gates (i,g,o only; f is dead) -> c, h  (FFMA2 row-pairs) ----------------
__global__ void k_lstm(const float* __restrict__ Wih,
                       const float* __restrict__ bih,
                       const float* __restrict__ bhh){
  __shared__ float Zs[16][68];
  __shared__ float Wg3[3][16][36];
  int mt = blockIdx.x, jt = blockIdx.y;
  int r0 = mt*64, j0 = jt*32;
  int tI = threadIdx.x;
  int tx = tI & 31, ty = tI >> 5;
  int m0 = ty*8;
  unsigned long long ai2[4], ag2[4], ao2[4];
  #pragma unroll
  for (int i = 0; i < 4; i++){ ai2[i]=0ull; ag2[i]=0ull; ao2[i]=0ull; }
  int lm = tI >> 2, lk = (tI & 3)*4;
  for (int kc = 0; kc < 12; kc++){
    int kb = kc*16;
    float4 zv = *(const float4*)(g_z + (size_t)(r0+lm)*ZC + kb + lk);
    float4 wv[2]; int wg[2], wj[2], wk[2]; bool wval[2];
    #pragma unroll
    for (int i = 0; i < 2; i++){
      int idx = tI + i*256; wval[i] = idx < 384;
      wg[i]=0; wj[i]=0; wk[i]=0;
      if (wval[i]){
        wg[i] = idx/128; int rs = idx%128; wj[i] = rs>>2; wk[i] = (rs&3)*4;
        int baser = (wg[i]==0?0:(wg[i]==1?256:384)) + j0 + wj[i];
        wv[i] = *(const float4*)(Wih + (size_t)baser*ZC + kb + wk[i]);
      }
    }
    __syncthreads();
    Zs[lk+0][lm]=zv.x; Zs[lk+1][lm]=zv.y; Zs[lk+2][lm]=zv.z; Zs[lk+3][lm]=zv.w;
    #pragma unroll
    for (int i = 0; i < 2; i++){
      if (wval[i]){
        Wg3[wg[i]][wk[i]+0][wj[i]]=wv[i].x; Wg3[wg[i]][wk[i]+1][wj[i]]=wv[i].y;
        Wg3[wg[i]][wk[i]+2][wj[i]]=wv[i].z; Wg3[wg[i]][wk[i]+3][wj[i]]=wv[i].w;
      }
    }
    __syncthreads();
    #pragma unroll
    for (int kk = 0; kk < 16; kk++){
      ulonglong2 zp0 = *(const ulonglong2*)(&Zs[kk][m0]);
      ulonglong2 zp1 = *(const ulonglong2*)(&Zs[kk][m0+4]);
      float wi = Wg3[0][kk][tx], wgg = Wg3[1][kk][tx], wo = Wg3[2][kk][tx];
      unsigned long long wi2, wg2v, wo2;
      PACK2(wi2, wi); PACK2(wg2v, wgg); PACK2(wo2, wo);
      FMA2(ai2[0], zp0.x, wi2);  FMA2(ai2[1], zp0.y, wi2);
      FMA2(ai2[2], zp1.x, wi2);  FMA2(ai2[3], zp1.y, wi2);
      FMA2(ag2[0], zp0.x, wg2v); FMA2(ag2[1], zp0.y, wg2v);
      FMA2(ag2[2], zp1.x, wg2v); FMA2(ag2[3], zp1.y, wg2v);
      FMA2(ao2[0], zp0.x, wo2);  FMA2(ao2[1], zp0.y, wo2);
      FMA2(ao2[2], zp1.x, wo2);  FMA2(ao2[3], zp1.y, wo2);
    }
    __syncthreads();
  }
  float ai[8], ag[8], ao[8];
  #pragma unroll
  for (int i = 0; i < 4; i++){
    UNPACK2(ai[2*i], ai[2*i+1], ai2[i]);
    UNPACK2(ag[2*i], ag[2*i+1], ag2[i]);
    UNPACK2(ao[2*i], ao[2*i+1], ao2[i]);
  }
  int j = j0 + tx;
  float bi_ = bih[j]       + bhh[j];
  float bg_ = bih[256 + j] + bhh[256 + j];
  float bo_ = bih[384 + j] + bhh[384 + j];
  #pragma unroll
  for (int i = 0; i < 8; i++){
    int r = r0 + m0 + i;
    float ci = sigf(ai[i]+bi_)*tanhf(ag[i]+bg_);
    float hh = sigf(ao[i]+bo_)*tanhf(ci);
    g_c[(size_t)r*HIDN + j] = ci;
    g_h[(size_t)r*HIDN + j] = hh;
  }
}

// ---------------- output head o = h @ Wout^T + bout (+ op write, + xp write) ----------------
__global__ void k_out(const float* __restrict__ Wout, const float* __restrict__ bout,
                      const float* __restrict__ x, float* __restrict__ out,
                      int wr_op, int kstep, int wr_xp, int xpk){
  int warp = threadIdx.x >> 5, lane = threadIdx.x & 31;
  int r = blockIdx.x*8 + warp;
  float hv[4];
  #pragma unroll
  for (int i = 0; i < 4; i++) hv[i] = g_h[(size_t)r*HIDN + lane + i*32];
  float res[5];
  #pragma unroll
  for (int c = 0; c < 5; c++){
    float s = 0.f;
    #pragma unroll
    for (int i = 0; i < 4; i++) s += hv[i]*__ldg(Wout + c*HIDN + lane + i*32);
    #pragma unroll
    for (int d = 16; d > 0; d >>= 1) s += __shfl_xor_sync(0xffffffffu, s, d);
    res[c] = s + bout[c];
  }
  if (lane == 0){
    int b = r & 31, p = r >> 5;
    #pragma unroll
    for (int c = 0; c < 5; c++){
      g_o[r*OUTN + c] = res[c];
      if (wr_op)
        out[(size_t)XP_ELEMS + ((size_t)(b*PREDN + kstep)*Psz + p)*OUTN + c] = res[c];
    }
    if (wr_xp){
      float pid = x[((size_t)(b*Ssz + Ssz-1)*Psz + p)*3 + 0];
      size_t base = ((size_t)(b*PREDN + xpk)*Psz + p)*3;
      out[base+0] = pid;
      out[base+1] = res[0];
      out[base+2] = res[1];
    }
  }
}

// ---------------- launch ----------------
extern "C" void kernel_launch(void* const* d_in, const int* in_sizes, int n_in,
                              void* d_out, int out_size){
  const float* x    = (const float*)d_in[0];
  const float* Win  = (const float*)d_in[1];
  const float* bin  = (const float*)d_in[2];
  const float* Wsoc = (const float*)d_in[3];
  const float* bsoc = (const float*)d_in[4];
  const float* bprev= (const float*)d_in[5];
  const float* Wih  = (const float*)d_in[6];
  const float* bih  = (const float*)d_in[7];
  const float* bhh  = (const float*)d_in[8];
  const float* Wout = (const float*)d_in[9];
  const float* bout = (const float*)d_in[10];
  float* out = (float*)d_out;

  const int DYN = (Psz*HIDN + PT*HS_STR)*(int)sizeof(float);
  cudaFuncSetAttribute(k_fused, cudaFuncAttributeMaxDynamicSharedMemorySize, DYN);

  k_init<<<(RROWS*HIDN + 255)/256, 256>>>(bprev);
  k_wt<<<(HIDN*2048 + 255)/256, 256>>>(Wsoc);
  for (int t = 0; t < OBSN; t++){
    k_mask<<<Psz, Psz>>>(x, t, 0);
    k_fused<<<dim3(Bsz, Psz/PT), 256, DYN>>>(x, bsoc, Win, bin, t, 0);
    k_lstm<<<dim3(RROWS/64, 4), 256>>>(Wih, bih, bhh);
    if (t == OBSN-1)
      k_out<<<RROWS/8, 256>>>(Wout, bout, x, out, 0, 0, 1, 0);   // g_o + xp[0]
  }
  for (int k = 0; k < PREDN; k++){
    k_mask<<<Psz, Psz>>>(x, 0, 1);
    k_fused<<<dim3(Bsz, Psz/PT), 256, DYN>>>(x, bsoc, Win, bin, 0, 1);
    k_lstm<<<dim3(RROWS/64, 4), 256>>>(Wih, bih, bhh);
    k_out<<<RROWS/8, 256>>>(Wout, bout, x, out, 1, k, (k < PREDN-1) ? 1 : 0, k+1);
  }
}

// round 10
// speedup vs baseline: 1.3106x; 1.0525x over previous
#include <cuda_runtime.h>
#include <math.h>

#define Bsz   32
#define Ssz   20
#define Psz   256
#define HIDN  128
#define MIDN  64
#define G2N   16
#define OBSN  8
#define PREDN 12
#define OUTN  5
#define RROWS (Psz*Bsz)          // 8192 rows, r = p*32 + b  (p-major)
#define ZC    (MIDN+HIDN)        // 192
#define XP_ELEMS (Bsz*PREDN*Psz*3)   // 294912

// ---- packed fp32x2 helpers (sm_100+): bit-exact per-lane f32 ops ----
#define PACK2(d, s)      asm("mov.b64 %0, {%1, %1};" : "=l"(d) : "f"(s))
#define UNPACK2(lo,hi,s) asm("mov.b64 {%0, %1}, %2;" : "=f"(lo), "=f"(hi) : "l"(s))
#define FMA2(d, a, b)    asm("fma.rn.f32x2 %0, %1, %2, %0;" : "+l"(d) : "l"(a), "l"(b))
#define ADD2(d, a)       asm("add.rn.f32x2 %0, %0, %1;" : "+l"(d) : "l"(a))

// ---------------- device scratch ----------------
__device__ float g_c[RROWS*HIDN];          // carry (cell state), 4 MB
__device__ float g_z[RROWS*ZC];            // [e | a], 6 MB
__device__ float g_h[RROWS*HIDN];          // hidden h, 4 MB
__device__ float g_o[RROWS*OUTN];          // last output
__device__ float g_Wt[2048*HIDN];          // W_soc transposed [k][n], 1 MB
__device__ unsigned char g_list[Psz*Psz];  // per-p neighbor ids grouped by cell
__device__ int g_off[Psz*(G2N+1)];         // per-p per-cell offsets
__device__ unsigned int g_active[Psz];     // per-p active-cell bitmask

__device__ __forceinline__ float sigf(float x){ return 1.f/(1.f+expf(-x)); }

// ---------------- init carry = relu(b_prev) broadcast ----------------
__global__ void k_init(const float* __restrict__ bprev){
  int i = blockIdx.x*256 + threadIdx.x;
  if (i < RROWS*HIDN){ float v = bprev[i & (HIDN-1)]; g_c[i] = v > 0.f ? v : 0.f; }
}

// ---------------- one-time transpose of W_soc [128][2048] -> g_Wt [2048][128] ----------------
__global__ void k_wt(const float* __restrict__ Wsoc){
  int i = blockIdx.x*256 + threadIdx.x;     // i over 128*2048
  if (i < HIDN*2048){
    int n = i >> 11, k = i & 2047;
    g_Wt[k*HIDN + n] = Wsoc[i];
  }
}

// ---------------- mask + bucketed neighbor lists + active bitmask (R0-proven) ----------------
__global__ void k_mask(const float* __restrict__ x, int t, int pred){
  __shared__ float spid[Psz], spx[Psz], spy[Psz];
  __shared__ unsigned char garr[Psz];
  __shared__ int cnt[G2N], off[G2N+1];
  int p = blockIdx.x, q = threadIdx.x;
  if (pred){
    spid[q] = x[((size_t)(Ssz-1)*Psz + q)*3 + 0];
    spx[q]  = g_o[(q*Bsz + 0)*OUTN + 0];
    spy[q]  = g_o[(q*Bsz + 0)*OUTN + 1];
  } else {
    const float* xb = x + (size_t)(t*Psz)*3;
    spid[q] = xb[q*3+0]; spx[q] = xb[q*3+1]; spy[q] = xb[q*3+2];
  }
  __syncthreads();
  const float Rx = 0.2f, Ry = 0.2f, CELLF = 0.1f;
  float lx = spx[p]-Rx, rxb = spx[p]+Rx, by = spy[p]-Ry, ty = spy[p]+Ry;
  float ox = spx[q], oy = spy[q];
  bool inb   = (ox < rxb) && (ox >= lx) && (oy < ty) && (oy >= by);
  bool valid = (spid[p] != 0.f) && (spid[q] != 0.f) && (spid[p] != spid[q]);
  int cx = (int)floorf((ox - lx)/CELLF);
  int cy = (int)floorf((oy - by)/CELLF);
  int idx = cx + cy*4; idx = idx < 0 ? 0 : (idx > 15 ? 15 : idx);
  garr[q] = (inb && valid) ? (unsigned char)idx : (unsigned char)255;
  __syncthreads();
  if (q < G2N){
    int c = 0;
    for (int o = 0; o < Psz; o++) if (garr[o] == (unsigned char)q) c++;
    cnt[q] = c;
  }
  __syncthreads();
  if (q == 0){
    int s = 0; unsigned int act = 0;
    for (int g = 0; g < G2N; g++){ off[g] = s; if (cnt[g]) act |= (1u<<g); s += cnt[g]; }
    off[G2N] = s;
    g_active[p] = act;
    for (int g = 0; g <= G2N; g++) g_off[p*(G2N+1)+g] = off[g];
  }
  __syncthreads();
  if (q < G2N){
    int w = off[q];
    for (int o = 0; o < Psz; o++)
      if (garr[o] == (unsigned char)q) g_list[p*Psz + (w++)] = (unsigned char)o;
  }
}

// ---- hsum build for one cell: EXACT dual-accumulator even/odd order (bit-exact) ----
__device__ __forceinline__ void build_cell(
    int g, float* __restrict__ hsb, int wl, int tx,
    const float4* __restrict__ cs4,
    const unsigned char* __restrict__ ls,
    const int* __restrict__ offs){
  #pragma unroll
  for (int i2 = 0; i2 < 8; i2++){
    int pl = wl*8 + i2;
    int s = offs[pl*17 + g], e = offs[pl*17 + g + 1];
    unsigned long long a0lo = 0ull, a0hi = 0ull, a1lo = 0ull, a1hi = 0ull;
    int j = s;
    for (; j+1 < e; j += 2){
      ulonglong2 v0 = *(const ulonglong2*)(cs4 + (int)ls[pl*Psz + j]*32 + tx);
      ulonglong2 v1 = *(const ulonglong2*)(cs4 + (int)ls[pl*Psz + j+1]*32 + tx);
      ADD2(a0lo, v0.x); ADD2(a0hi, v0.y);
      ADD2(a1lo, v1.x); ADD2(a1hi, v1.y);
    }
    if (j < e){
      ulonglong2 v0 = *(const ulonglong2*)(cs4 + (int)ls[pl*Psz + j]*32 + tx);
      ADD2(a0lo, v0.x); ADD2(a0hi, v0.y);
    }
    ADD2(a0lo, a1lo); ADD2(a0hi, a1hi);
    *(ulonglong2*)(hsb + pl*132 + tx*4) = make_ulonglong2(a0lo, a0hi);
  }
}

// ---------------- fused hsum||GEMM producer/consumer pipeline + e, writes z ----------------
// Block = (b, 64-p tile), 512 threads = 16 warps.
// Warps 0-7: soc GEMM (8x4 tile/thread, FFMA2) on hs buffer A.
// Warps 8-15: build next cell's hsum into hs buffer B (identical code/order).
#define PT     64
#define HS_STR 132
__global__ void __launch_bounds__(512, 1) k_fused(
    const float* __restrict__ x,
    const float* __restrict__ bsoc,
    const float* __restrict__ Win,
    const float* __restrict__ bin,
    int t, int pred){
  extern __shared__ float dyn[];
  float* cs  = dyn;                        // 256*128 floats = 128 KB
  float* hs0 = dyn + Psz*HIDN;             // 64*132 floats
  float* hs1 = hs0 + PT*HS_STR;            // 64*132 floats
  __shared__ unsigned char ls[PT*Psz];     // 16 KB neighbor lists
  __shared__ int offs[PT*(G2N+1)];
  __shared__ int gl[G2N];
  __shared__ int s_ng;

  int b = blockIdx.x, pbase = blockIdx.y*PT;
  int tid = threadIdx.x;
  float4* cs4 = (float4*)cs;

  // load c[:,b,:] (all 256 p rows for this b)
  for (int i = tid; i < Psz*HIDN/4; i += 512){
    int o = i>>5, q = i&31;
    cs4[i] = *(const float4*)(g_c + ((size_t)o*Bsz + b)*HIDN + q*4);
  }
  // neighbor lists + offsets for this p-tile (contiguous copy)
  for (int i = tid; i < PT*Psz/16; i += 512)
    ((uint4*)ls)[i] = ((const uint4*)(g_list + (size_t)pbase*Psz))[i];
  for (int i = tid; i < PT*(G2N+1); i += 512)
    offs[i] = g_off[pbase*(G2N+1) + i];
  if (tid == 0){
    unsigned int u = 0;
    for (int pp = 0; pp < PT; pp++) u |= g_active[pbase+pp];
    int n = 0;
    for (int g = 0; g < G2N; g++) if ((u>>g)&1u) gl[n++] = g;
    s_ng = n;
  }
  __syncthreads();
  int ng = s_ng;

  int tx = tid & 31, wid = tid >> 5;    // 16 warps
  int group = wid >> 3, wl = wid & 7;   // group 0: GEMM, group 1: producer
  int n0 = tx*4, m0 = wl*8;
  unsigned long long acc01[8], acc23[8];
  #pragma unroll
  for (int i = 0; i < 8; i++){ acc01[i] = 0ull; acc23[i] = 0ull; }

  if (ng > 0){
    // producers build cell 0 into hs0
    if (group == 1) build_cell(gl[0], hs0, wl, tx, cs4, ls, offs);
    __syncthreads();
    for (int gi = 0; gi < ng; gi++){
      if (group == 0){
        // ---- GEMM warps: consume hs buffer (gi&1) for cell gl[gi] ----
        const float* hsb = (gi & 1) ? hs1 : hs0;
        const float* Wg = g_Wt + (size_t)gl[gi]*128*HIDN + n0;
        #pragma unroll 2
        for (int kc = 0; kc < 8; kc++){
          #pragma unroll
          for (int kq = 0; kq < 4; kq++){
            float4 hv[8];
            #pragma unroll
            for (int i = 0; i < 8; i++)
              hv[i] = *(const float4*)(hsb + (m0+i)*HS_STR + kc*16 + kq*4);
            #pragma unroll
            for (int kk = 0; kk < 4; kk++){
              ulonglong2 wp = *(const ulonglong2*)(Wg + (size_t)(kc*16 + kq*4 + kk)*HIDN);
              #pragma unroll
              for (int i = 0; i < 8; i++){
                float h = ((const float*)&hv[i])[kk];
                unsigned long long h2;
                PACK2(h2, h);
                FMA2(acc01[i], h2, wp.x);
                FMA2(acc23[i], h2, wp.y);
              }
            }
          }
        }
      } else if (gi + 1 < ng){
        // ---- producer warps: build next cell into the other buffer ----
        build_cell(gl[gi+1], ((gi+1) & 1) ? hs1 : hs0, wl, tx, cs4, ls, offs);
      }
      __syncthreads();
    }
  }

  // ---- epilogue: a = relu(acc + b_soc) -> z[:,64:192]  (GEMM warps only) ----
  if (group == 0){
    float4 bv = *(const float4*)(bsoc + n0);
    #pragma unroll
    for (int i = 0; i < 8; i++){
      int r = (pbase + m0 + i)*Bsz + b;
      float a0, a1, a2, a3;
      UNPACK2(a0, a1, acc01[i]);
      UNPACK2(a2, a3, acc23[i]);
      float4 o;
      o.x = fmaxf(a0 + bv.x, 0.f);
      o.y = fmaxf(a1 + bv.y, 0.f);
      o.z = fmaxf(a2 + bv.z, 0.f);
      o.w = fmaxf(a3 + bv.w, 0.f);
      *(float4*)(g_z + (size_t)r*ZC + MIDN + n0) = o;
    }
  }
  // ---- e = relu(pos @ Win^T + bin) -> z[:,0:64]  (all threads) ----
  for (int i2 = tid; i2 < PT*MIDN; i2 += 512){
    int mm = i2 >> 6, j = i2 & 63;
    int p = pbase + mm;
    int r = p*Bsz + b;
    float px, py;
    if (pred){ px = g_o[r*OUTN+0]; py = g_o[r*OUTN+1]; }
    else {
      const float* xr = x + (size_t)(((b*Ssz)+t)*Psz + p)*3;
      px = xr[1]; py = xr[2];
    }
    float v = px*Win[j*2+0] + py*Win[j*2+1] + bin[j];
    g_z[(size_t)r*ZC + j] = v > 0.f ? v : 0.f;
  }
}

// ---------------- LSTM gates (i,g,o only; f is dead) -> c, h  (FFMA2 row-pairs) ----------------
__global__ void k_lstm(const float* __restrict__ Wih,
                       const float* __restrict__ bih,
                       const float* __restrict__ bhh){
  __shared__ float Zs[16][68];
  __shared__ float Wg3[3][16][36];
  int mt = blockIdx.x, jt = blockIdx.y;
  int r0 = mt*64, j0 = jt*32;
  int tI = threadIdx.x;
  int tx = tI & 31, ty = tI >> 5;
  int m0 = ty*8;
  unsigned long long ai2[4], ag2[4], ao2[4];
  #pragma unroll
  for (int i = 0; i < 4; i++){ ai2[i]=0ull; ag2[i]=0ull; ao2[i]=0ull; }
  int lm = tI >> 2, lk = (tI & 3)*4;
  for (int kc = 0; kc < 12; kc++){
    int kb = kc*16;
    float4 zv = *(const float4*)(g_z + (size_t)(r0+lm)*ZC + kb + lk);
    float4 wv[2]; int wg[2], wj[2], wk[2]; bool wval[2];
    #pragma unroll
    for (int i = 0; i < 2; i++){
      int idx = tI + i*256; wval[i] = idx < 384;
      wg[i]=0; wj[i]=0; wk[i]=0;
      if (wval[i]){
        wg[i] = idx/128; int rs = idx%128; wj[i] = rs>>2; wk[i] = (rs&3)*4;
        int baser = (wg[i]==0?0:(wg[i]==1?256:384)) + j0 + wj[i];
        wv[i] = *(const float4*)(Wih + (size_t)baser*ZC + kb + wk[i]);
      }
    }
    __syncthreads();
    Zs[lk+0][lm]=zv.x; Zs[lk+1][lm]=zv.y; Zs[lk+2][lm]=zv.z; Zs[lk+3][lm]=zv.w;
    #pragma unroll
    for (int i = 0; i < 2; i++){
      if (wval[i]){
        Wg3[wg[i]][wk[i]+0][wj[i]]=wv[i].x; Wg3[wg[i]][wk[i]+1][wj[i]]=wv[i].y;
        Wg3[wg[i]][wk[i]+2][wj[i]]=wv[i].z; Wg3[wg[i]][wk[i]+3][wj[i]]=wv[i].w;
      }
    }
    __syncthreads();
    #pragma unroll
    for (int kk = 0; kk < 16; kk++){
      ulonglong2 zp0 = *(const ulonglong2*)(&Zs[kk][m0]);
      ulonglong2 zp1 = *(const ulonglong2*)(&Zs[kk][m0+4]);
      float wi = Wg3[0][kk][tx], wgg = Wg3[1][kk][tx], wo = Wg3[2][kk][tx];
      unsigned long long wi2, wg2v, wo2;
      PACK2(wi2, wi); PACK2(wg2v, wgg); PACK2(wo2, wo);
      FMA2(ai2[0], zp0.x, wi2);  FMA2(ai2[1], zp0.y, wi2);
      FMA2(ai2[2], zp1.x, wi2);  FMA2(ai2[3], zp1.y, wi2);
      FMA2(ag2[0], zp0.x, wg2v); FMA2(ag2[1], zp0.y, wg2v);
      FMA2(ag2[2], zp1.x, wg2v); FMA2(ag2[3], zp1.y, wg2v);
      FMA2(ao2[0], zp0.x, wo2);  FMA2(ao2[1], zp0.y, wo2);
      FMA2(ao2[2], zp1.x, wo2);  FMA2(ao2[3], zp1.y, wo2);
    }
    __syncthreads();
  }
  float ai[8], ag[8], ao[8];
  #pragma unroll
  for (int i = 0; i < 4; i++){
    UNPACK2(ai[2*i], ai[2*i+1], ai2[i]);
    UNPACK2(ag[2*i], ag[2*i+1], ag2[i]);
    UNPACK2(ao[2*i], ao[2*i+1], ao2[i]);
  }
  int j = j0 + tx;
  float bi_ = bih[j]       + bhh[j];
  float bg_ = bih[256 + j] + bhh[256 + j];
  float bo_ = bih[384 + j] + bhh[384 + j];
  #pragma unroll
  for (int i = 0; i < 8; i++){
    int r = r0 + m0 + i;
    float ci = sigf(ai[i]+bi_)*tanhf(ag[i]+bg_);
    float hh = sigf(ao[i]+bo_)*tanhf(ci);
    g_c[(size_t)r*HIDN + j] = ci;
    g_h[(size_t)r*HIDN + j] = hh;
  }
}

// ---------------- output head o = h @ Wout^T + bout (+ op write, + xp write) ----------------
__global__ void k_out(const float* __restrict__ Wout, const float* __restrict__ bout,
                      const float* __restrict__ x, float* __restrict__ out,
                      int wr_op, int kstep, int wr_xp, int xpk){
  int warp = threadIdx.x >> 5, lane = threadIdx.x & 31;
  int r = blockIdx.x*8 + warp;
  float hv[4];
  #pragma unroll
  for (int i = 0; i < 4; i++) hv[i] = g_h[(size_t)r*HIDN + lane + i*32];
  float res[5];
  #pragma unroll
  for (int c = 0; c < 5; c++){
    float s = 0.f;
    #pragma unroll
    for (int i = 0; i < 4; i++) s += hv[i]*__ldg(Wout + c*HIDN + lane + i*32);
    #pragma unroll
    for (int d = 16; d > 0; d >>= 1) s += __shfl_xor_sync(0xffffffffu, s, d);
    res[c] = s + bout[c];
  }
  if (lane == 0){
    int b = r & 31, p = r >> 5;
    #pragma unroll
    for (int c = 0; c < 5; c++){
      g_o[r*OUTN + c] = res[c];
      if (wr_op)
        out[(size_t)XP_ELEMS + ((size_t)(b*PREDN + kstep)*Psz + p)*OUTN + c] = res[c];
    }
    if (wr_xp){
      float pid = x[((size_t)(b*Ssz + Ssz-1)*Psz + p)*3 + 0];
      size_t base = ((size_t)(b*PREDN + xpk)*Psz + p)*3;
      out[base+0] = pid;
      out[base+1] = res[0];
      out[base+2] = res[1];
    }
  }
}

// ---------------- launch ----------------
extern "C" void kernel_launch(void* const* d_in, const int* in_sizes, int n_in,
                              void* d_out, int out_size){
  const float* x    = (const float*)d_in[0];
  const float* Win  = (const float*)d_in[1];
  const float* bin  = (const float*)d_in[2];
  const float* Wsoc = (const float*)d_in[3];
  const float* bsoc = (const float*)d_in[4];
  const float* bprev= (const float*)d_in[5];
  const float* Wih  = (const float*)d_in[6];
  const float* bih  = (const float*)d_in[7];
  const float* bhh  = (const float*)d_in[8];
  const float* Wout = (const float*)d_in[9];
  const float* bout = (const float*)d_in[10];
  float* out = (float*)d_out;

  const int DYN = (Psz*HIDN + 2*PT*HS_STR)*(int)sizeof(float);
  cudaFuncSetAttribute(k_fused, cudaFuncAttributeMaxDynamicSharedMemorySize, DYN);

  k_init<<<(RROWS*HIDN + 255)/256, 256>>>(bprev);
  k_wt<<<(HIDN*2048 + 255)/256, 256>>>(Wsoc);
  for (int t = 0; t < OBSN; t++){
    k_mask<<<Psz, Psz>>>(x, t, 0);
    k_fused<<<dim3(Bsz, Psz/PT), 512, DYN>>>(x, bsoc, Win, bin, t, 0);
    k_lstm<<<dim3(RROWS/64, 4), 256>>>(Wih, bih, bhh);
    if (t == OBSN-1)
      k_out<<<RROWS/8, 256>>>(Wout, bout, x, out, 0, 0, 1, 0);   // g_o + xp[0]
  }
  for (int k = 0; k < PREDN; k++){
    k_mask<<<Psz, Psz>>>(x, 0, 1);
    k_fused<<<dim3(Bsz, Psz/PT), 512, DYN>>>(x, bsoc, Win, bin, 0, 1);
    k_lstm<<<dim3(RROWS/64, 4), 256>>>(Wih, bih, bhh);
    k_out<<<RROWS/8, 256>>>(Wout, bout, x, out, 1, k, (k < PREDN-1) ? 1 : 0, k+1);
  }
}

// round 11
// speedup vs baseline: 1.3637x; 1.0405x over previous
#include <cuda_runtime.h>
#include <math.h>

#define Bsz   32
#define Ssz   20
#define Psz   256
#define HIDN  128
#define MIDN  64
#define G2N   16
#define OBSN  8
#define PREDN 12
#define OUTN  5
#define RROWS (Psz*Bsz)          // 8192 rows, r = p*32 + b  (p-major)
#define ZC    (MIDN+HIDN)        // 192
#define XP_ELEMS (Bsz*PREDN*Psz*3)   // 294912

// ---- packed fp32x2 helpers (sm_100+): bit-exact per-lane f32 ops ----
#define PACK2(d, s)      asm("mov.b64 %0, {%1, %1};" : "=l"(d) : "f"(s))
#define UNPACK2(lo,hi,s) asm("mov.b64 {%0, %1}, %2;" : "=f"(lo), "=f"(hi) : "l"(s))
#define FMA2(d, a, b)    asm("fma.rn.f32x2 %0, %1, %2, %0;" : "+l"(d) : "l"(a), "l"(b))
#define ADD2(d, a)       asm("add.rn.f32x2 %0, %0, %1;" : "+l"(d) : "l"(a))

// ---------------- device scratch ----------------
__device__ float g_c[RROWS*HIDN];          // carry (cell state), 4 MB
__device__ float g_h[RROWS*HIDN];          // hidden h, 4 MB
__device__ float g_o[RROWS*OUTN];          // last output
__device__ float g_Wt[2048*HIDN];          // W_soc transposed [k][n], 1 MB
__device__ float g_Wt2[ZC*384];            // W_ih (i,g,o rows) transposed [k][384]
__device__ unsigned char g_list[Psz*Psz];  // per-p neighbor ids grouped by cell
__device__ int g_off[Psz*(G2N+1)];         // per-p per-cell offsets
__device__ unsigned int g_active[Psz];     // per-p active-cell bitmask

__device__ __forceinline__ float sigf(float x){ return 1.f/(1.f+expf(-x)); }

// ---------------- init carry = relu(b_prev) broadcast ----------------
__global__ void k_init(const float* __restrict__ bprev){
  int i = blockIdx.x*256 + threadIdx.x;
  if (i < RROWS*HIDN){ float v = bprev[i & (HIDN-1)]; g_c[i] = v > 0.f ? v : 0.f; }
}

// ---------------- one-time transpose of W_soc [128][2048] -> g_Wt [2048][128] ----------------
__global__ void k_wt(const float* __restrict__ Wsoc){
  int i = blockIdx.x*256 + threadIdx.x;     // i over 128*2048
  if (i < HIDN*2048){
    int n = i >> 11, k = i & 2047;
    g_Wt[k*HIDN + n] = Wsoc[i];
  }
}

// ---------------- one-time transpose of W_ih (rows i,g,o) -> g_Wt2 [192][384] ----------------
// flattened jj: [0,128)=i rows jj; [128,256)=g rows jj+128; [256,384)=o rows jj+128
__global__ void k_wt2(const float* __restrict__ Wih){
  int i = blockIdx.x*256 + threadIdx.x;     // i over 192*384
  if (i < ZC*384){
    int k = i / 384, jj = i % 384;
    int row = (jj < 128) ? jj : jj + 128;
    g_Wt2[k*384 + jj] = Wih[(size_t)row*ZC + k];
  }
}

// ---------------- mask + bucketed neighbor lists + active bitmask (R0-proven) ----------------
__global__ void k_mask(const float* __restrict__ x, int t, int pred){
  __shared__ float spid[Psz], spx[Psz], spy[Psz];
  __shared__ unsigned char garr[Psz];
  __shared__ int cnt[G2N], off[G2N+1];
  int p = blockIdx.x, q = threadIdx.x;
  if (pred){
    spid[q] = x[((size_t)(Ssz-1)*Psz + q)*3 + 0];
    spx[q]  = g_o[(q*Bsz + 0)*OUTN + 0];
    spy[q]  = g_o[(q*Bsz + 0)*OUTN + 1];
  } else {
    const float* xb = x + (size_t)(t*Psz)*3;
    spid[q] = xb[q*3+0]; spx[q] = xb[q*3+1]; spy[q] = xb[q*3+2];
  }
  __syncthreads();
  const float Rx = 0.2f, Ry = 0.2f, CELLF = 0.1f;
  float lx = spx[p]-Rx, rxb = spx[p]+Rx, by = spy[p]-Ry, ty = spy[p]+Ry;
  float ox = spx[q], oy = spy[q];
  bool inb   = (ox < rxb) && (ox >= lx) && (oy < ty) && (oy >= by);
  bool valid = (spid[p] != 0.f) && (spid[q] != 0.f) && (spid[p] != spid[q]);
  int cx = (int)floorf((ox - lx)/CELLF);
  int cy = (int)floorf((oy - by)/CELLF);
  int idx = cx + cy*4; idx = idx < 0 ? 0 : (idx > 15 ? 15 : idx);
  garr[q] = (inb && valid) ? (unsigned char)idx : (unsigned char)255;
  __syncthreads();
  if (q < G2N){
    int c = 0;
    for (int o = 0; o < Psz; o++) if (garr[o] == (unsigned char)q) c++;
    cnt[q] = c;
  }
  __syncthreads();
  if (q == 0){
    int s = 0; unsigned int act = 0;
    for (int g = 0; g < G2N; g++){ off[g] = s; if (cnt[g]) act |= (1u<<g); s += cnt[g]; }
    off[G2N] = s;
    g_active[p] = act;
    for (int g = 0; g <= G2N; g++) g_off[p*(G2N+1)+g] = off[g];
  }
  __syncthreads();
  if (q < G2N){
    int w = off[q];
    for (int o = 0; o < Psz; o++)
      if (garr[o] == (unsigned char)q) g_list[p*Psz + (w++)] = (unsigned char)o;
  }
}

// ---- hsum build for one cell: EXACT dual-accumulator even/odd order (bit-exact) ----
__device__ __forceinline__ void build_cell(
    int g, float* __restrict__ hsb, int wl, int tx,
    const float4* __restrict__ cs4,
    const unsigned char* __restrict__ ls,
    const int* __restrict__ offs){
  #pragma unroll
  for (int i2 = 0; i2 < 8; i2++){
    int pl = wl*8 + i2;
    int s = offs[pl*17 + g], e = offs[pl*17 + g + 1];
    unsigned long long a0lo = 0ull, a0hi = 0ull, a1lo = 0ull, a1hi = 0ull;
    int j = s;
    for (; j+1 < e; j += 2){
      ulonglong2 v0 = *(const ulonglong2*)(cs4 + (int)ls[pl*Psz + j]*32 + tx);
      ulonglong2 v1 = *(const ulonglong2*)(cs4 + (int)ls[pl*Psz + j+1]*32 + tx);
      ADD2(a0lo, v0.x); ADD2(a0hi, v0.y);
      ADD2(a1lo, v1.x); ADD2(a1hi, v1.y);
    }
    if (j < e){
      ulonglong2 v0 = *(const ulonglong2*)(cs4 + (int)ls[pl*Psz + j]*32 + tx);
      ADD2(a0lo, v0.x); ADD2(a0hi, v0.y);
    }
    ADD2(a0lo, a1lo); ADD2(a0hi, a1hi);
    *(ulonglong2*)(hsb + pl*132 + tx*4) = make_ulonglong2(a0lo, a0hi);
  }
}

// ---------------- fused: hsum||socGEMM pipeline + e + LSTM + c,h ----------------
// Block = (b, 64-p tile), 512 threads = 16 warps.
// Phase A: warps 0-7 soc GEMM (FFMA2), warps 8-15 hsum producer (double buffer).
// Phase B: z=[e|a] -> smem zs[64][196]; in-block LSTM gate GEMM vs g_Wt2
//          (per-(row,j) chain strictly k ascending, fma.rn == k_lstm bit-exact);
//          gate partials -> gsum (overlays cs); gates -> g_c, g_h.
#define PT     64
#define HS_STR 132
#define ZS_STR 196
#define WS2    388
__global__ void __launch_bounds__(512, 1) k_fused(
    const float* __restrict__ x,
    const float* __restrict__ bsoc,
    const float* __restrict__ Win,
    const float* __restrict__ bin,
    const float* __restrict__ bih,
    const float* __restrict__ bhh,
    int t, int pred){
  extern __shared__ float dyn[];
  float* cs  = dyn;                        // 256*128 floats = 128 KB (phase A)
  float* hs0 = dyn + Psz*HIDN;             // 64*132 floats
  float* hs1 = hs0 + PT*HS_STR;            // 64*132 floats
  // phase B overlays (cs/hs dead):
  float* zs     = dyn;                     // 64*196 floats
  float* wstage = dyn + PT*ZS_STR;         // 16*388 floats
  float* gsum   = wstage + 16*WS2;         // 64*388 floats
  __shared__ unsigned char ls[PT*Psz];     // 16 KB neighbor lists
  __shared__ int offs[PT*(G2N+1)];
  __shared__ int gl[G2N];
  __shared__ int s_ng;

  int b = blockIdx.x, pbase = blockIdx.y*PT;
  int tid = threadIdx.x;
  float4* cs4 = (float4*)cs;

  // load c[:,b,:] (all 256 p rows for this b)
  for (int i = tid; i < Psz*HIDN/4; i += 512){
    int o = i>>5, q = i&31;
    cs4[i] = *(const float4*)(g_c + ((size_t)o*Bsz + b)*HIDN + q*4);
  }
  // neighbor lists + offsets for this p-tile (contiguous copy)
  for (int i = tid; i < PT*Psz/16; i += 512)
    ((uint4*)ls)[i] = ((const uint4*)(g_list + (size_t)pbase*Psz))[i];
  for (int i = tid; i < PT*(G2N+1); i += 512)
    offs[i] = g_off[pbase*(G2N+1) + i];
  if (tid == 0){
    unsigned int u = 0;
    for (int pp = 0; pp < PT; pp++) u |= g_active[pbase+pp];
    int n = 0;
    for (int g = 0; g < G2N; g++) if ((u>>g)&1u) gl[n++] = g;
    s_ng = n;
  }
  __syncthreads();
  int ng = s_ng;

  int tx = tid & 31, wid = tid >> 5;    // 16 warps
  int group = wid >> 3, wl = wid & 7;   // group 0: GEMM, group 1: producer
  int n0 = tx*4, m0 = wl*8;
  unsigned long long acc01[8], acc23[8];
  #pragma unroll
  for (int i = 0; i < 8; i++){ acc01[i] = 0ull; acc23[i] = 0ull; }

  if (ng > 0){
    if (group == 1) build_cell(gl[0], hs0, wl, tx, cs4, ls, offs);
    __syncthreads();
    for (int gi = 0; gi < ng; gi++){
      if (group == 0){
        const float* hsb = (gi & 1) ? hs1 : hs0;
        const float* Wg = g_Wt + (size_t)gl[gi]*128*HIDN + n0;
        #pragma unroll 2
        for (int kc = 0; kc < 8; kc++){
          #pragma unroll
          for (int kq = 0; kq < 4; kq++){
            float4 hv[8];
            #pragma unroll
            for (int i = 0; i < 8; i++)
              hv[i] = *(const float4*)(hsb + (m0+i)*HS_STR + kc*16 + kq*4);
            #pragma unroll
            for (int kk = 0; kk < 4; kk++){
              ulonglong2 wp = *(const ulonglong2*)(Wg + (size_t)(kc*16 + kq*4 + kk)*HIDN);
              #pragma unroll
              for (int i = 0; i < 8; i++){
                float h = ((const float*)&hv[i])[kk];
                unsigned long long h2;
                PACK2(h2, h);
                FMA2(acc01[i], h2, wp.x);
                FMA2(acc23[i], h2, wp.y);
              }
            }
          }
        }
      } else if (gi + 1 < ng){
        build_cell(gl[gi+1], ((gi+1) & 1) ? hs1 : hs0, wl, tx, cs4, ls, offs);
      }
      __syncthreads();
    }
  }

  // ================= Phase B =================
  // B1: e = relu(pos @ Win^T + bin) -> zs[:,0:64]   (all threads; same expr as before)
  for (int i2 = tid; i2 < PT*MIDN; i2 += 512){
    int mm = i2 >> 6, j = i2 & 63;
    int p = pbase + mm;
    int r = p*Bsz + b;
    float px, py;
    if (pred){ px = g_o[r*OUTN+0]; py = g_o[r*OUTN+1]; }
    else {
      const float* xr = x + (size_t)(((b*Ssz)+t)*Psz + p)*3;
      px = xr[1]; py = xr[2];
    }
    float v = px*Win[j*2+0] + py*Win[j*2+1] + bin[j];
    zs[mm*ZS_STR + j] = v > 0.f ? v : 0.f;
  }
  // B1b: a = relu(acc + b_soc) -> zs[:,64:192]   (GEMM warps hold acc)
  if (group == 0){
    float4 bv = *(const float4*)(bsoc + n0);
    #pragma unroll
    for (int i = 0; i < 8; i++){
      float a0, a1, a2, a3;
      UNPACK2(a0, a1, acc01[i]);
      UNPACK2(a2, a3, acc23[i]);
      float4 o;
      o.x = fmaxf(a0 + bv.x, 0.f);
      o.y = fmaxf(a1 + bv.y, 0.f);
      o.z = fmaxf(a2 + bv.z, 0.f);
      o.w = fmaxf(a3 + bv.w, 0.f);
      *(float4*)(zs + (m0+i)*ZS_STR + MIDN + n0) = o;
    }
  }
  __syncthreads();

  // B2: LSTM gate GEMM: gsum[row][jj] = sum_{k=0..191} zs[row][k] * Wt2[k][jj]
  // thread: rows m2..m2+7, j-pairs (j0,j0+1),(j0+2,j0+3),(j0+4,j0+5)
  {
    int jpg = tid & 63, rowg = tid >> 6;
    int j0 = jpg*6, m2 = rowg*8;
    unsigned long long lacc[24];
    #pragma unroll
    for (int i = 0; i < 24; i++) lacc[i] = 0ull;
    for (int kc = 0; kc < 12; kc++){
      // stage Wt2 chunk [16 k][384 j]
      #pragma unroll
      for (int s3 = 0; s3 < 3; s3++){
        int idx = s3*512 + tid;           // 0..1535
        int kk = idx / 96, v4 = idx % 96;
        *(float4*)(wstage + kk*WS2 + v4*4) =
          *(const float4*)(g_Wt2 + (size_t)(kc*16 + kk)*384 + v4*4);
      }
      __syncthreads();
      #pragma unroll 4
      for (int kk = 0; kk < 16; kk++){
        int k = kc*16 + kk;
        unsigned long long h2[8];
        #pragma unroll
        for (int i = 0; i < 8; i++){
          float hv = zs[(m2+i)*ZS_STR + k];   // broadcast within warp
          PACK2(h2[i], hv);
        }
        #pragma unroll
        for (int jj = 0; jj < 3; jj++){
          unsigned long long w2 = *(const unsigned long long*)(wstage + kk*WS2 + j0 + 2*jj);
          #pragma unroll
          for (int i = 0; i < 8; i++)
            FMA2(lacc[i*3+jj], h2[i], w2);
        }
      }
      __syncthreads();
    }
    // write gate partial sums
    #pragma unroll
    for (int i = 0; i < 8; i++)
      #pragma unroll
      for (int jj = 0; jj < 3; jj++)
        *(unsigned long long*)(gsum + (m2+i)*WS2 + j0 + 2*jj) = lacc[i*3+jj];
  }
  __syncthreads();

  // B3: gates -> c, h  (exact k_lstm formulas/order)
  for (int idx = tid; idx < PT*HIDN; idx += 512){
    int row = idx >> 7, jH = idx & 127;
    float ai = gsum[row*WS2 + jH];
    float ag = gsum[row*WS2 + 128 + jH];
    float ao = gsum[row*WS2 + 256 + jH];
    float bi_ = bih[jH]       + bhh[jH];
    float bg_ = bih[256 + jH] + bhh[256 + jH];
    float bo_ = bih[384 + jH] + bhh[384 + jH];
    float ci = sigf(ai+bi_)*tanhf(ag+bg_);
    float hh = sigf(ao+bo_)*tanhf(ci);
    int r = (pbase + row)*Bsz + b;
    g_c[(size_t)r*HIDN + jH] = ci;
    g_h[(size_t)r*HIDN + jH] = hh;
  }
}

// ---------------- output head o = h @ Wout^T + bout (+ op write, + xp write) ----------------
__global__ void k_out(const float* __restrict__ Wout, const float* __restrict__ bout,
                      const float* __restrict__ x, float* __restrict__ out,
                      int wr_op, int kstep, int wr_xp, int xpk){
  int warp = threadIdx.x >> 5, lane = threadIdx.x & 31;
  int r = blockIdx.x*8 + warp;
  float hv[4];
  #pragma unroll
  for (int i = 0; i < 4; i++) hv[i] = g_h[(size_t)r*HIDN + lane + i*32];
  float res[5];
  #pragma unroll
  for (int c = 0; c < 5; c++){
    float s = 0.f;
    #pragma unroll
    for (int i = 0; i < 4; i++) s += hv[i]*__ldg(Wout + c*HIDN + lane + i*32);
    #pragma unroll
    for (int d = 16; d > 0; d >>= 1) s += __shfl_xor_sync(0xffffffffu, s, d);
    res[c] = s + bout[c];
  }
  if (lane == 0){
    int b = r & 31, p = r >> 5;
    #pragma unroll
    for (int c = 0; c < 5; c++){
      g_o[r*OUTN + c] = res[c];
      if (wr_op)
        out[(size_t)XP_ELEMS + ((size_t)(b*PREDN + kstep)*Psz + p)*OUTN + c] = res[c];
    }
    if (wr_xp){
      float pid = x[((size_t)(b*Ssz + Ssz-1)*Psz + p)*3 + 0];
      size_t base = ((size_t)(b*PREDN + xpk)*Psz + p)*3;
      out[base+0] = pid;
      out[base+1] = res[0];
      out[base+2] = res[1];
    }
  }
}

// ---------------- launch ----------------
extern "C" void kernel_launch(void* const* d_in, const int* in_sizes, int n_in,
                              void* d_out, int out_size){
  const float* x    = (const float*)d_in[0];
  const float* Win  = (const float*)d_in[1];
  const float* bin  = (const float*)d_in[2];
  const float* Wsoc = (const float*)d_in[3];
  const float* bsoc = (const float*)d_in[4];
  const float* bprev= (const float*)d_in[5];
  const float* Wih  = (const float*)d_in[6];
  const float* bih  = (const float*)d_in[7];
  const float* bhh  = (const float*)d_in[8];
  const float* Wout = (const float*)d_in[9];
  const float* bout = (const float*)d_in[10];
  float* out = (float*)d_out;

  const int DYN_A = (Psz*HIDN + 2*PT*HS_STR)*(int)sizeof(float);
  const int DYN_B = (PT*ZS_STR + 16*WS2 + PT*WS2)*(int)sizeof(float);
  const int DYN = DYN_A > DYN_B ? DYN_A : DYN_B;
  cudaFuncSetAttribute(k_fused, cudaFuncAttributeMaxDynamicSharedMemorySize, DYN);

  k_init<<<(RROWS*HIDN + 255)/256, 256>>>(bprev);
  k_wt<<<(HIDN*2048 + 255)/256, 256>>>(Wsoc);
  k_wt2<<<(ZC*384 + 255)/256, 256>>>(Wih);
  for (int t = 0; t < OBSN; t++){
    k_mask<<<Psz, Psz>>>(x, t, 0);
    k_fused<<<dim3(Bsz, Psz/PT), 512, DYN>>>(x, bsoc, Win, bin, bih, bhh, t, 0);
    if (t == OBSN-1)
      k_out<<<RROWS/8, 256>>>(Wout, bout, x, out, 0, 0, 1, 0);   // g_o + xp[0]
  }
  for (int k = 0; k < PREDN; k++){
    k_mask<<<Psz, Psz>>>(x, 0, 1);
    k_fused<<<dim3(Bsz, Psz/PT), 512, DYN>>>(x, bsoc, Win, bin, bih, bhh, 0, 1);
    k_out<<<RROWS/8, 256>>>(Wout, bout, x, out, 1, k, (k < PREDN-1) ? 1 : 0, k+1);
  }
}